// round 1
// baseline (speedup 1.0000x reference)
#include <cuda_runtime.h>

#define DIMSZ 2048
#define NHEADS 16
#define HDIM 128
#define BSZ 2
#define LSEQ 2048
#define MROWS (BSZ * LSEQ)   // 4096

// Scratch (allocation-free rule: __device__ globals)
__device__ float g_q[(size_t)MROWS * DIMSZ];        // 32 MB
__device__ float g_kv[(size_t)MROWS * 2 * DIMSZ];   // 64 MB  (k | v)
__device__ float g_attn[(size_t)MROWS * DIMSZ];     // 32 MB

// ---------------------------------------------------------------------------
// SGEMM: C[M,N] = A[M,K] @ B[K,N] + bias[N]
// A row-major lda=K, B row-major leading dim ldb, C row-major ldc=N.
// Tile 128x128x16, 256 threads, 8x8 per thread (split as 2x(4) in each dim).
// ---------------------------------------------------------------------------
__global__ __launch_bounds__(256)
void sgemm_bias(const float* __restrict__ A, const float* __restrict__ B,
                const float* __restrict__ bias, float* __restrict__ C,
                int M, int N, int K, int ldb)
{
    __shared__ float As[16][132];
    __shared__ float Bs[16][132];

    const int t  = threadIdx.x;
    const int m0 = blockIdx.y * 128;
    const int n0 = blockIdx.x * 128;
    const int tm = t >> 4;   // 0..15
    const int tn = t & 15;   // 0..15

    float acc[8][8];
#pragma unroll
    for (int i = 0; i < 8; i++)
#pragma unroll
        for (int j = 0; j < 8; j++) acc[i][j] = 0.f;

    for (int k0 = 0; k0 < K; k0 += 16) {
        // Load A tile [128 x 16] -> As transposed [16][128]
#pragma unroll
        for (int i = 0; i < 2; i++) {
            int idx = i * 256 + t;
            int row = idx >> 2;       // 0..127
            int kq  = idx & 3;        // 0..3 (float4 along k)
            float4 a = *(const float4*)&A[(size_t)(m0 + row) * K + k0 + kq * 4];
            As[kq * 4 + 0][row] = a.x;
            As[kq * 4 + 1][row] = a.y;
            As[kq * 4 + 2][row] = a.z;
            As[kq * 4 + 3][row] = a.w;
        }
        // Load B tile [16 x 128]
#pragma unroll
        for (int i = 0; i < 2; i++) {
            int idx = i * 256 + t;
            int kr = idx >> 5;        // 0..15
            int n4 = idx & 31;        // 0..31 (float4 along n)
            *(float4*)&Bs[kr][n4 * 4] =
                *(const float4*)&B[(size_t)(k0 + kr) * ldb + n0 + n4 * 4];
        }
        __syncthreads();

#pragma unroll
        for (int kk = 0; kk < 16; kk++) {
            float ra[8], rb[8];
            *(float4*)&ra[0] = *(const float4*)&As[kk][tm * 4];
            *(float4*)&ra[4] = *(const float4*)&As[kk][64 + tm * 4];
            *(float4*)&rb[0] = *(const float4*)&Bs[kk][tn * 4];
            *(float4*)&rb[4] = *(const float4*)&Bs[kk][64 + tn * 4];
#pragma unroll
            for (int i = 0; i < 8; i++)
#pragma unroll
                for (int j = 0; j < 8; j++)
                    acc[i][j] = fmaf(ra[i], rb[j], acc[i][j]);
        }
        __syncthreads();
    }

    // Epilogue: bias + store (rows/cols split in 2 halves of 4)
#pragma unroll
    for (int i = 0; i < 8; i++) {
        int m = m0 + ((i < 4) ? (tm * 4 + i) : (64 + tm * 4 + i - 4));
#pragma unroll
        for (int jh = 0; jh < 2; jh++) {
            int n = n0 + jh * 64 + tn * 4;
            float4 bv = *(const float4*)&bias[n];
            float4 o;
            o.x = acc[i][jh * 4 + 0] + bv.x;
            o.y = acc[i][jh * 4 + 1] + bv.y;
            o.z = acc[i][jh * 4 + 2] + bv.z;
            o.w = acc[i][jh * 4 + 3] + bv.w;
            *(float4*)&C[(size_t)m * N + n] = o;
        }
    }
}

// ---------------------------------------------------------------------------
// Flash attention (fp32): per block = (b, h, 64 q-rows), streams K/V in 64-row
// tiles with online softmax. 256 threads.
//   S phase:  thread = (rg = t/16 -> rows rg*4..+3, cg = t%16 -> cols cg+16j)
//   O phase:  thread = rows rg*4..+3, cols cg*4..+3 and 64+cg*4..+3
// Shared: Qs/Ks/Vs [64][132], Ps [64][64], row_m/row_l [64]
// ---------------------------------------------------------------------------
#define ATT_STRIDE 132
#define ATT_SMEM_FLOATS (3 * 64 * ATT_STRIDE + 64 * 64 + 2 * 64)

__global__ __launch_bounds__(256)
void attn_kernel(const float* __restrict__ Q, const float* __restrict__ KV,
                 float* __restrict__ O)
{
    extern __shared__ float sh[];
    float* Qs    = sh;
    float* Ks    = Qs + 64 * ATT_STRIDE;
    float* Vs    = Ks + 64 * ATT_STRIDE;
    float* Ps    = Vs + 64 * ATT_STRIDE;
    float* row_m = Ps + 64 * 64;
    float* row_l = row_m + 64;

    const int t  = threadIdx.x;
    const int rg = t >> 4;    // 0..15  -> rows rg*4..rg*4+3
    const int cg = t & 15;    // 0..15
    const int b  = blockIdx.z;
    const int h  = blockIdx.y;
    const int q0 = blockIdx.x * 64;

    const size_t qbase  = ((size_t)(b * LSEQ + q0)) * DIMSZ + (size_t)h * HDIM;
    const size_t kvrow0 = (size_t)b * LSEQ;
    const float scale   = 0.08838834764831845f;   // 1/sqrt(128)

    // Load Q tile [64 x 128]
#pragma unroll
    for (int i = 0; i < 8; i++) {
        int idx = i * 256 + t;
        int row = idx >> 5;   // 0..63
        int d4  = idx & 31;   // 0..31
        *(float4*)&Qs[row * ATT_STRIDE + d4 * 4] =
            *(const float4*)&Q[qbase + (size_t)row * DIMSZ + d4 * 4];
    }
    if (t < 64) { row_m[t] = -3.0e38f; row_l[t] = 0.f; }

    float o[4][2][4];
#pragma unroll
    for (int i = 0; i < 4; i++)
#pragma unroll
        for (int jh = 0; jh < 2; jh++)
#pragma unroll
            for (int j = 0; j < 4; j++) o[i][jh][j] = 0.f;

    for (int jt = 0; jt < LSEQ / 64; jt++) {
        __syncthreads();  // Q visible (first iter) / previous O-phase done with Ks,Vs,Ps

        // Load K and V tiles [64 x 128]
        const int k0 = jt * 64;
#pragma unroll
        for (int i = 0; i < 8; i++) {
            int idx = i * 256 + t;
            int row = idx >> 5;
            int d4  = idx & 31;
            size_t base = (kvrow0 + k0 + row) * (size_t)(2 * DIMSZ)
                          + (size_t)h * HDIM + d4 * 4;
            *(float4*)&Ks[row * ATT_STRIDE + d4 * 4] = *(const float4*)&KV[base];
            *(float4*)&Vs[row * ATT_STRIDE + d4 * 4] = *(const float4*)&KV[base + DIMSZ];
        }
        __syncthreads();

        // ---- S = Q K^T (thread: 4 rows x 4 strided cols) ----
        float s[4][4];
#pragma unroll
        for (int i = 0; i < 4; i++)
#pragma unroll
            for (int j = 0; j < 4; j++) s[i][j] = 0.f;

#pragma unroll 8
        for (int d = 0; d < HDIM; d += 4) {
            float4 qv[4], kv[4];
#pragma unroll
            for (int i = 0; i < 4; i++)
                qv[i] = *(const float4*)&Qs[(rg * 4 + i) * ATT_STRIDE + d];
#pragma unroll
            for (int j = 0; j < 4; j++)
                kv[j] = *(const float4*)&Ks[(cg + 16 * j) * ATT_STRIDE + d];
#pragma unroll
            for (int i = 0; i < 4; i++)
#pragma unroll
                for (int j = 0; j < 4; j++) {
                    s[i][j] = fmaf(qv[i].x, kv[j].x, s[i][j]);
                    s[i][j] = fmaf(qv[i].y, kv[j].y, s[i][j]);
                    s[i][j] = fmaf(qv[i].z, kv[j].z, s[i][j]);
                    s[i][j] = fmaf(qv[i].w, kv[j].w, s[i][j]);
                }
        }

        // ---- online softmax update ----
        float new_m[4], tsum[4], rscale[4], old_l[4];
#pragma unroll
        for (int i = 0; i < 4; i++) {
            float mx = -3.0e38f;
#pragma unroll
            for (int j = 0; j < 4; j++) { s[i][j] *= scale; mx = fmaxf(mx, s[i][j]); }
#pragma unroll
            for (int off = 1; off < 16; off <<= 1)
                mx = fmaxf(mx, __shfl_xor_sync(0xffffffffu, mx, off));
            float old_m = row_m[rg * 4 + i];
            new_m[i] = fmaxf(old_m, mx);
            float sum = 0.f;
#pragma unroll
            for (int j = 0; j < 4; j++) { float p = __expf(s[i][j] - new_m[i]); s[i][j] = p; sum += p; }
#pragma unroll
            for (int off = 1; off < 16; off <<= 1)
                sum += __shfl_xor_sync(0xffffffffu, sum, off);
            tsum[i]   = sum;
            rscale[i] = __expf(old_m - new_m[i]);
        }
        // Write P
#pragma unroll
        for (int i = 0; i < 4; i++)
#pragma unroll
            for (int j = 0; j < 4; j++)
                Ps[(rg * 4 + i) * 64 + cg + 16 * j] = s[i][j];
        if (cg == 0) {
#pragma unroll
            for (int i = 0; i < 4; i++) old_l[i] = row_l[rg * 4 + i];
        }
        __syncthreads();
        if (cg == 0) {
#pragma unroll
            for (int i = 0; i < 4; i++) {
                row_l[rg * 4 + i] = old_l[i] * rscale[i] + tsum[i];
                row_m[rg * 4 + i] = new_m[i];
            }
        }

        // ---- O = O*rscale + P @ V ----
#pragma unroll
        for (int i = 0; i < 4; i++)
#pragma unroll
            for (int jh = 0; jh < 2; jh++)
#pragma unroll
                for (int j = 0; j < 4; j++) o[i][jh][j] *= rscale[i];

#pragma unroll 4
        for (int k = 0; k < 64; k++) {
            float p0 = Ps[(rg * 4 + 0) * 64 + k];
            float p1 = Ps[(rg * 4 + 1) * 64 + k];
            float p2 = Ps[(rg * 4 + 2) * 64 + k];
            float p3 = Ps[(rg * 4 + 3) * 64 + k];
            float4 v0 = *(const float4*)&Vs[k * ATT_STRIDE + cg * 4];
            float4 v1 = *(const float4*)&Vs[k * ATT_STRIDE + 64 + cg * 4];
            o[0][0][0] = fmaf(p0, v0.x, o[0][0][0]); o[0][0][1] = fmaf(p0, v0.y, o[0][0][1]);
            o[0][0][2] = fmaf(p0, v0.z, o[0][0][2]); o[0][0][3] = fmaf(p0, v0.w, o[0][0][3]);
            o[0][1][0] = fmaf(p0, v1.x, o[0][1][0]); o[0][1][1] = fmaf(p0, v1.y, o[0][1][1]);
            o[0][1][2] = fmaf(p0, v1.z, o[0][1][2]); o[0][1][3] = fmaf(p0, v1.w, o[0][1][3]);
            o[1][0][0] = fmaf(p1, v0.x, o[1][0][0]); o[1][0][1] = fmaf(p1, v0.y, o[1][0][1]);
            o[1][0][2] = fmaf(p1, v0.z, o[1][0][2]); o[1][0][3] = fmaf(p1, v0.w, o[1][0][3]);
            o[1][1][0] = fmaf(p1, v1.x, o[1][1][0]); o[1][1][1] = fmaf(p1, v1.y, o[1][1][1]);
            o[1][1][2] = fmaf(p1, v1.z, o[1][1][2]); o[1][1][3] = fmaf(p1, v1.w, o[1][1][3]);
            o[2][0][0] = fmaf(p2, v0.x, o[2][0][0]); o[2][0][1] = fmaf(p2, v0.y, o[2][0][1]);
            o[2][0][2] = fmaf(p2, v0.z, o[2][0][2]); o[2][0][3] = fmaf(p2, v0.w, o[2][0][3]);
            o[2][1][0] = fmaf(p2, v1.x, o[2][1][0]); o[2][1][1] = fmaf(p2, v1.y, o[2][1][1]);
            o[2][1][2] = fmaf(p2, v1.z, o[2][1][2]); o[2][1][3] = fmaf(p2, v1.w, o[2][1][3]);
            o[3][0][0] = fmaf(p3, v0.x, o[3][0][0]); o[3][0][1] = fmaf(p3, v0.y, o[3][0][1]);
            o[3][0][2] = fmaf(p3, v0.z, o[3][0][2]); o[3][0][3] = fmaf(p3, v0.w, o[3][0][3]);
            o[3][1][0] = fmaf(p3, v1.x, o[3][1][0]); o[3][1][1] = fmaf(p3, v1.y, o[3][1][1]);
            o[3][1][2] = fmaf(p3, v1.z, o[3][1][2]); o[3][1][3] = fmaf(p3, v1.w, o[3][1][3]);
        }
    }

    __syncthreads();  // final row_l visible
#pragma unroll
    for (int i = 0; i < 4; i++) {
        float inv = 1.0f / row_l[rg * 4 + i];
        size_t orow = ((size_t)(b * LSEQ + q0 + rg * 4 + i)) * DIMSZ + (size_t)h * HDIM;
        float4 a;
        a.x = o[i][0][0] * inv; a.y = o[i][0][1] * inv;
        a.z = o[i][0][2] * inv; a.w = o[i][0][3] * inv;
        *(float4*)&O[orow + cg * 4] = a;
        a.x = o[i][1][0] * inv; a.y = o[i][1][1] * inv;
        a.z = o[i][1][2] * inv; a.w = o[i][1][3] * inv;
        *(float4*)&O[orow + 64 + cg * 4] = a;
    }
}

// ---------------------------------------------------------------------------
extern "C" void kernel_launch(void* const* d_in, const int* in_sizes, int n_in,
                              void* d_out, int out_size)
{
    const float* x       = (const float*)d_in[0];
    const float* context = (const float*)d_in[1];
    const float* W_qkv   = (const float*)d_in[2];
    const float* b_qkv   = (const float*)d_in[3];
    const float* W_proj  = (const float*)d_in[4];
    const float* b_proj  = (const float*)d_in[5];
    float* out = (float*)d_out;

    float *qb = nullptr, *kvb = nullptr, *attnb = nullptr;
    cudaGetSymbolAddress((void**)&qb,    g_q);
    cudaGetSymbolAddress((void**)&kvb,   g_kv);
    cudaGetSymbolAddress((void**)&attnb, g_attn);

    // 1) q = x @ W_qkv[:, :2048] + b_qkv[:2048]
    sgemm_bias<<<dim3(DIMSZ / 128, MROWS / 128), 256>>>(
        x, W_qkv, b_qkv, qb, MROWS, DIMSZ, DIMSZ, 3 * DIMSZ);

    // 2) kv = context @ W_qkv[:, 2048:] + b_qkv[2048:]   (N = 4096)
    sgemm_bias<<<dim3(2 * DIMSZ / 128, MROWS / 128), 256>>>(
        context, W_qkv + DIMSZ, b_qkv + DIMSZ, kvb, MROWS, 2 * DIMSZ, DIMSZ, 3 * DIMSZ);

    // 3) attention
    static const size_t att_smem = (size_t)ATT_SMEM_FLOATS * sizeof(float);
    cudaFuncSetAttribute(attn_kernel, cudaFuncAttributeMaxDynamicSharedMemorySize,
                         (int)att_smem);
    attn_kernel<<<dim3(LSEQ / 64, NHEADS, BSZ), 256, att_smem>>>(qb, kvb, attnb);

    // 4) out = attn @ W_proj + b_proj
    sgemm_bias<<<dim3(DIMSZ / 128, MROWS / 128), 256>>>(
        attnb, W_proj, b_proj, out, MROWS, DIMSZ, DIMSZ, DIMSZ);
}

// round 3
// speedup vs baseline: 1.3804x; 1.3804x over previous
#include <cuda_runtime.h>
#include <cuda_bf16.h>
#include <cstdint>

#define DIMSZ 2048
#define NHEADS 16
#define HDIM 128
#define BSZ 2
#define LSEQ 2048
#define MROWS (BSZ * LSEQ)   // 4096
#define KDIM 2048

// ---------------------------------------------------------------------------
// Scratch (__device__ globals; no allocation allowed)
// ---------------------------------------------------------------------------
__device__ float g_q[(size_t)MROWS * DIMSZ];
__device__ float g_kv[(size_t)MROWS * 2 * DIMSZ];
__device__ float g_attn[(size_t)MROWS * DIMSZ];

__device__ __nv_bfloat16 g_xh[(size_t)MROWS * DIMSZ];
__device__ __nv_bfloat16 g_xl[(size_t)MROWS * DIMSZ];
__device__ __nv_bfloat16 g_ch[(size_t)MROWS * DIMSZ];
__device__ __nv_bfloat16 g_cl[(size_t)MROWS * DIMSZ];
__device__ __nv_bfloat16 g_wqh[(size_t)3 * DIMSZ * DIMSZ];  // W_qkv^T [6144][2048]
__device__ __nv_bfloat16 g_wql[(size_t)3 * DIMSZ * DIMSZ];
__device__ __nv_bfloat16 g_wph[(size_t)DIMSZ * DIMSZ];      // W_proj^T [2048][2048]
__device__ __nv_bfloat16 g_wpl[(size_t)DIMSZ * DIMSZ];
__device__ __nv_bfloat16 g_ath[(size_t)MROWS * DIMSZ];
__device__ __nv_bfloat16 g_atl[(size_t)MROWS * DIMSZ];

// ---------------------------------------------------------------------------
// PTX helpers (baseline ISA only: ldmatrix / mma.sync / cp.async)
// ---------------------------------------------------------------------------
__device__ __forceinline__ uint32_t smem_to_u32(const void* p) {
    uint32_t a;
    asm("{ .reg .u64 t; cvta.to.shared.u64 t, %1; cvt.u32.u64 %0, t; }" : "=r"(a) : "l"(p));
    return a;
}

#define CP_ASYNC16(dst, src) \
    asm volatile("cp.async.cg.shared.global [%0], [%1], 16;" :: "r"(dst), "l"(src) : "memory")
#define CP_COMMIT() asm volatile("cp.async.commit_group;" ::: "memory")
#define CP_WAIT(n)  asm volatile("cp.async.wait_group %0;" :: "n"(n) : "memory")

#define LDSM_X4(r0, r1, r2, r3, addr) \
    asm volatile("ldmatrix.sync.aligned.m8n8.x4.shared.b16 {%0,%1,%2,%3}, [%4];" \
                 : "=r"(r0), "=r"(r1), "=r"(r2), "=r"(r3) : "r"(addr))

#define MMA16816(d, a, b0, b1) \
    asm volatile("mma.sync.aligned.m16n8k16.row.col.f32.bf16.bf16.f32 " \
                 "{%0,%1,%2,%3}, {%4,%5,%6,%7}, {%8,%9}, {%0,%1,%2,%3};" \
                 : "+f"((d)[0]), "+f"((d)[1]), "+f"((d)[2]), "+f"((d)[3]) \
                 : "r"((a)[0]), "r"((a)[1]), "r"((a)[2]), "r"((a)[3]), \
                   "r"(b0), "r"(b1))

// ---------------------------------------------------------------------------
// Conversion kernels: fp32 -> (hi, lo) bf16 split
// ---------------------------------------------------------------------------
__global__ __launch_bounds__(256)
void split_fp32(const float* __restrict__ in, __nv_bfloat16* __restrict__ h,
                __nv_bfloat16* __restrict__ l, int n4)
{
    int i = blockIdx.x * 256 + threadIdx.x;
    if (i >= n4) return;
    float4 v = ((const float4*)in)[i];
    __nv_bfloat16 h0 = __float2bfloat16(v.x), h1 = __float2bfloat16(v.y);
    __nv_bfloat16 h2 = __float2bfloat16(v.z), h3 = __float2bfloat16(v.w);
    __nv_bfloat16 l0 = __float2bfloat16(v.x - __bfloat162float(h0));
    __nv_bfloat16 l1 = __float2bfloat16(v.y - __bfloat162float(h1));
    __nv_bfloat16 l2 = __float2bfloat16(v.z - __bfloat162float(h2));
    __nv_bfloat16 l3 = __float2bfloat16(v.w - __bfloat162float(h3));
    __nv_bfloat162* H = (__nv_bfloat162*)h;
    __nv_bfloat162* L = (__nv_bfloat162*)l;
    __nv_bfloat162 t;
    t.x = h0; t.y = h1; H[2 * i] = t;
    t.x = h2; t.y = h3; H[2 * i + 1] = t;
    t.x = l0; t.y = l1; L[2 * i] = t;
    t.x = l2; t.y = l3; L[2 * i + 1] = t;
}

// in [R][C] fp32 row-major -> out [C][R] bf16 hi/lo (transposed)
__global__ __launch_bounds__(256)
void transpose_split(const float* __restrict__ in, __nv_bfloat16* __restrict__ h,
                     __nv_bfloat16* __restrict__ l, int R, int C)
{
    __shared__ float tile[32][33];
    int c0 = blockIdx.x * 32, r0 = blockIdx.y * 32;
    int tx = threadIdx.x & 31, ty = threadIdx.x >> 5;
#pragma unroll
    for (int i = 0; i < 4; i++)
        tile[ty + 8 * i][tx] = in[(size_t)(r0 + ty + 8 * i) * C + c0 + tx];
    __syncthreads();
#pragma unroll
    for (int i = 0; i < 4; i++) {
        float v = tile[tx][ty + 8 * i];
        __nv_bfloat16 hv = __float2bfloat16(v);
        __nv_bfloat16 lv = __float2bfloat16(v - __bfloat162float(hv));
        size_t o = (size_t)(c0 + ty + 8 * i) * R + r0 + tx;
        h[o] = hv; l[o] = lv;
    }
}

// ---------------------------------------------------------------------------
// mma.sync split-bf16 GEMM: C[M,N] = A[M,K] @ B^T[N,K] + bias  (3 passes)
// CTA 128x128x32, 8 warps (warp tile 32m x 64n), double-buffered cp.async.
// Smem rows padded to 80 B (40 bf16) -> conflict-free ldmatrix.
// ---------------------------------------------------------------------------
#define GBK 32
#define NCH (KDIM / GBK)        // 64
#define ROWB 80                  // bytes per smem row
#define TILE_B (128 * ROWB)      // 10240
#define STAGE_B (4 * TILE_B)     // 40960: [Ah][Al][Bh][Bl]
#define GEMM_SMEM (2 * STAGE_B)  // 81920

__global__ __launch_bounds__(256, 1)
void gemm_mma(const __nv_bfloat16* __restrict__ Ah0, const __nv_bfloat16* __restrict__ Al0,
              const __nv_bfloat16* __restrict__ Ah1, const __nv_bfloat16* __restrict__ Al1,
              const __nv_bfloat16* __restrict__ Bh, const __nv_bfloat16* __restrict__ Bl,
              const float* __restrict__ bias,
              float* __restrict__ C0, int ldc0, float* __restrict__ C1, int ldc1, int nsplit)
{
    extern __shared__ char sm[];
    const uint32_t sbase = smem_to_u32(sm);
    const int tid  = threadIdx.x;
    const int lane = tid & 31;
    const int wid  = tid >> 5;
    const int wm   = (wid & 3) * 32;   // warp m offset
    const int wn   = (wid >> 2) * 64;  // warp n offset
    const int n0 = blockIdx.x * 128;
    const int m0 = blockIdx.y * 128;

    const __nv_bfloat16* Ah = (n0 < nsplit) ? Ah0 : Ah1;
    const __nv_bfloat16* Al = (n0 < nsplit) ? Al0 : Al1;

    float acc[2][8][4];
#pragma unroll
    for (int i = 0; i < 2; i++)
#pragma unroll
        for (int j = 0; j < 8; j++)
#pragma unroll
            for (int r = 0; r < 4; r++) acc[i][j][r] = 0.f;

    // Per-thread ldmatrix byte offsets (relative to a 128-row tile base)
    // A (x4, m-frag mf, k-step kk): row = mf*16 + (lane&15), col = kk + 8*(lane>>4)
    uint32_t aoff[2][2];
#pragma unroll
    for (int mf = 0; mf < 2; mf++)
#pragma unroll
        for (int ks = 0; ks < 2; ks++)
            aoff[mf][ks] = (uint32_t)((wm + mf * 16 + (lane & 15)) * ROWB
                                      + (ks * 16 + 8 * (lane >> 4)) * 2);
    // B (x4, n-frag pair jj, k-step kk): row = jj*16 + (lane&7) + 8*(lane>>4), col = kk + 8*((lane>>3)&1)
    uint32_t boff[4][2];
#pragma unroll
    for (int jj = 0; jj < 4; jj++)
#pragma unroll
        for (int ks = 0; ks < 2; ks++)
            boff[jj][ks] = (uint32_t)((wn + jj * 16 + (lane & 7) + 8 * (lane >> 4)) * ROWB
                                      + (ks * 16 + 8 * ((lane >> 3) & 1)) * 2);

    // cp.async loader: 2048 x 16B chunks (4 tiles x 128 rows x 4 segs)
    auto load_chunk = [&](int ic, int s) {
        const int k0 = ic * GBK;
#pragma unroll
        for (int it = 0; it < 8; it++) {
            const int tile   = it >> 1;                 // 0:Ah 1:Al 2:Bh 3:Bl
            const int within = (it & 1) * 256 + tid;    // 0..511
            const int row    = within >> 2;
            const int seg    = within & 3;
            const __nv_bfloat16* src;
            if (tile == 0)      src = Ah + (size_t)(m0 + row) * KDIM + k0 + seg * 8;
            else if (tile == 1) src = Al + (size_t)(m0 + row) * KDIM + k0 + seg * 8;
            else if (tile == 2) src = Bh + (size_t)(n0 + row) * KDIM + k0 + seg * 8;
            else                src = Bl + (size_t)(n0 + row) * KDIM + k0 + seg * 8;
            uint32_t dst = sbase + s * STAGE_B + tile * TILE_B + row * ROWB + seg * 16;
            CP_ASYNC16(dst, src);
        }
        CP_COMMIT();
    };

    load_chunk(0, 0);

    for (int ic = 0; ic < NCH; ic++) {
        const int s = ic & 1;
        if (ic + 1 < NCH) { load_chunk(ic + 1, s ^ 1); CP_WAIT(1); }
        else              { CP_WAIT(0); }
        __syncthreads();

        const uint32_t stage = sbase + s * STAGE_B;
        // 3 passes: (Ah,Bh), (Ah,Bl), (Al,Bh)
#pragma unroll
        for (int pass = 0; pass < 3; pass++) {
            const uint32_t Abase = stage + ((pass == 2) ? TILE_B : 0);
            const uint32_t Bbase = stage + 2 * TILE_B + ((pass == 1) ? TILE_B : 0);
#pragma unroll
            for (int ks = 0; ks < 2; ks++) {
                uint32_t a[2][4];
                LDSM_X4(a[0][0], a[0][1], a[0][2], a[0][3], Abase + aoff[0][ks]);
                LDSM_X4(a[1][0], a[1][1], a[1][2], a[1][3], Abase + aoff[1][ks]);
#pragma unroll
                for (int jj = 0; jj < 4; jj++) {
                    uint32_t b0, b1, b2, b3;
                    LDSM_X4(b0, b1, b2, b3, Bbase + boff[jj][ks]);
                    MMA16816(acc[0][jj * 2],     a[0], b0, b1);
                    MMA16816(acc[1][jj * 2],     a[1], b0, b1);
                    MMA16816(acc[0][jj * 2 + 1], a[0], b2, b3);
                    MMA16816(acc[1][jj * 2 + 1], a[1], b2, b3);
                }
            }
        }
        __syncthreads();
    }

    // Epilogue: bias + fp32 store
    float* C; int ld, nc0;
    if (n0 < nsplit) { C = C0; ld = ldc0; nc0 = n0; }
    else             { C = C1; ld = ldc1; nc0 = n0 - nsplit; }

#pragma unroll
    for (int mf = 0; mf < 2; mf++) {
#pragma unroll
        for (int nf = 0; nf < 8; nf++) {
            const int nl = wn + nf * 8 + 2 * (lane & 3);   // local n
            const float bx = bias[n0 + nl];
            const float by = bias[n0 + nl + 1];
            const int m_up = m0 + wm + mf * 16 + (lane >> 2);
            float2 v;
            v.x = acc[mf][nf][0] + bx; v.y = acc[mf][nf][1] + by;
            *(float2*)(C + (size_t)m_up * ld + nc0 + nl) = v;
            v.x = acc[mf][nf][2] + bx; v.y = acc[mf][nf][3] + by;
            *(float2*)(C + (size_t)(m_up + 8) * ld + nc0 + nl) = v;
        }
    }
}

// ---------------------------------------------------------------------------
// Flash attention (fp32) — unchanged (known correct)
// ---------------------------------------------------------------------------
#define ATT_STRIDE 132
#define ATT_SMEM_FLOATS (3 * 64 * ATT_STRIDE + 64 * 64 + 2 * 64)

__global__ __launch_bounds__(256)
void attn_kernel(const float* __restrict__ Q, const float* __restrict__ KV,
                 float* __restrict__ O)
{
    extern __shared__ float sh[];
    float* Qs    = sh;
    float* Ks    = Qs + 64 * ATT_STRIDE;
    float* Vs    = Ks + 64 * ATT_STRIDE;
    float* Ps    = Vs + 64 * ATT_STRIDE;
    float* row_m = Ps + 64 * 64;
    float* row_l = row_m + 64;

    const int t  = threadIdx.x;
    const int rg = t >> 4;
    const int cg = t & 15;
    const int b  = blockIdx.z;
    const int h  = blockIdx.y;
    const int q0 = blockIdx.x * 64;

    const size_t qbase  = ((size_t)(b * LSEQ + q0)) * DIMSZ + (size_t)h * HDIM;
    const size_t kvrow0 = (size_t)b * LSEQ;
    const float scale   = 0.08838834764831845f;

#pragma unroll
    for (int i = 0; i < 8; i++) {
        int idx = i * 256 + t;
        int row = idx >> 5;
        int d4  = idx & 31;
        *(float4*)&Qs[row * ATT_STRIDE + d4 * 4] =
            *(const float4*)&Q[qbase + (size_t)row * DIMSZ + d4 * 4];
    }
    if (t < 64) { row_m[t] = -3.0e38f; row_l[t] = 0.f; }

    float o[4][2][4];
#pragma unroll
    for (int i = 0; i < 4; i++)
#pragma unroll
        for (int jh = 0; jh < 2; jh++)
#pragma unroll
            for (int j = 0; j < 4; j++) o[i][jh][j] = 0.f;

    for (int jt = 0; jt < LSEQ / 64; jt++) {
        __syncthreads();
        const int k0 = jt * 64;
#pragma unroll
        for (int i = 0; i < 8; i++) {
            int idx = i * 256 + t;
            int row = idx >> 5;
            int d4  = idx & 31;
            size_t base = (kvrow0 + k0 + row) * (size_t)(2 * DIMSZ)
                          + (size_t)h * HDIM + d4 * 4;
            *(float4*)&Ks[row * ATT_STRIDE + d4 * 4] = *(const float4*)&KV[base];
            *(float4*)&Vs[row * ATT_STRIDE + d4 * 4] = *(const float4*)&KV[base + DIMSZ];
        }
        __syncthreads();

        float s[4][4];
#pragma unroll
        for (int i = 0; i < 4; i++)
#pragma unroll
            for (int j = 0; j < 4; j++) s[i][j] = 0.f;

#pragma unroll 8
        for (int d = 0; d < HDIM; d += 4) {
            float4 qv[4], kv[4];
#pragma unroll
            for (int i = 0; i < 4; i++)
                qv[i] = *(const float4*)&Qs[(rg * 4 + i) * ATT_STRIDE + d];
#pragma unroll
            for (int j = 0; j < 4; j++)
                kv[j] = *(const float4*)&Ks[(cg + 16 * j) * ATT_STRIDE + d];
#pragma unroll
            for (int i = 0; i < 4; i++)
#pragma unroll
                for (int j = 0; j < 4; j++) {
                    s[i][j] = fmaf(qv[i].x, kv[j].x, s[i][j]);
                    s[i][j] = fmaf(qv[i].y, kv[j].y, s[i][j]);
                    s[i][j] = fmaf(qv[i].z, kv[j].z, s[i][j]);
                    s[i][j] = fmaf(qv[i].w, kv[j].w, s[i][j]);
                }
        }

        float new_m[4], tsum[4], rscale[4], old_l[4];
#pragma unroll
        for (int i = 0; i < 4; i++) {
            float mx = -3.0e38f;
#pragma unroll
            for (int j = 0; j < 4; j++) { s[i][j] *= scale; mx = fmaxf(mx, s[i][j]); }
#pragma unroll
            for (int off = 1; off < 16; off <<= 1)
                mx = fmaxf(mx, __shfl_xor_sync(0xffffffffu, mx, off));
            float old_m = row_m[rg * 4 + i];
            new_m[i] = fmaxf(old_m, mx);
            float sum = 0.f;
#pragma unroll
            for (int j = 0; j < 4; j++) { float p = __expf(s[i][j] - new_m[i]); s[i][j] = p; sum += p; }
#pragma unroll
            for (int off = 1; off < 16; off <<= 1)
                sum += __shfl_xor_sync(0xffffffffu, sum, off);
            tsum[i]   = sum;
            rscale[i] = __expf(old_m - new_m[i]);
        }
#pragma unroll
        for (int i = 0; i < 4; i++)
#pragma unroll
            for (int j = 0; j < 4; j++)
                Ps[(rg * 4 + i) * 64 + cg + 16 * j] = s[i][j];
        if (cg == 0) {
#pragma unroll
            for (int i = 0; i < 4; i++) old_l[i] = row_l[rg * 4 + i];
        }
        __syncthreads();
        if (cg == 0) {
#pragma unroll
            for (int i = 0; i < 4; i++) {
                row_l[rg * 4 + i] = old_l[i] * rscale[i] + tsum[i];
                row_m[rg * 4 + i] = new_m[i];
            }
        }

#pragma unroll
        for (int i = 0; i < 4; i++)
#pragma unroll
            for (int jh = 0; jh < 2; jh++)
#pragma unroll
                for (int j = 0; j < 4; j++) o[i][jh][j] *= rscale[i];

#pragma unroll 4
        for (int k = 0; k < 64; k++) {
            float p0 = Ps[(rg * 4 + 0) * 64 + k];
            float p1 = Ps[(rg * 4 + 1) * 64 + k];
            float p2 = Ps[(rg * 4 + 2) * 64 + k];
            float p3 = Ps[(rg * 4 + 3) * 64 + k];
            float4 v0 = *(const float4*)&Vs[k * ATT_STRIDE + cg * 4];
            float4 v1 = *(const float4*)&Vs[k * ATT_STRIDE + 64 + cg * 4];
            o[0][0][0] = fmaf(p0, v0.x, o[0][0][0]); o[0][0][1] = fmaf(p0, v0.y, o[0][0][1]);
            o[0][0][2] = fmaf(p0, v0.z, o[0][0][2]); o[0][0][3] = fmaf(p0, v0.w, o[0][0][3]);
            o[0][1][0] = fmaf(p0, v1.x, o[0][1][0]); o[0][1][1] = fmaf(p0, v1.y, o[0][1][1]);
            o[0][1][2] = fmaf(p0, v1.z, o[0][1][2]); o[0][1][3] = fmaf(p0, v1.w, o[0][1][3]);
            o[1][0][0] = fmaf(p1, v0.x, o[1][0][0]); o[1][0][1] = fmaf(p1, v0.y, o[1][0][1]);
            o[1][0][2] = fmaf(p1, v0.z, o[1][0][2]); o[1][0][3] = fmaf(p1, v0.w, o[1][0][3]);
            o[1][1][0] = fmaf(p1, v1.x, o[1][1][0]); o[1][1][1] = fmaf(p1, v1.y, o[1][1][1]);
            o[1][1][2] = fmaf(p1, v1.z, o[1][1][2]); o[1][1][3] = fmaf(p1, v1.w, o[1][1][3]);
            o[2][0][0] = fmaf(p2, v0.x, o[2][0][0]); o[2][0][1] = fmaf(p2, v0.y, o[2][0][1]);
            o[2][0][2] = fmaf(p2, v0.z, o[2][0][2]); o[2][0][3] = fmaf(p2, v0.w, o[2][0][3]);
            o[2][1][0] = fmaf(p2, v1.x, o[2][1][0]); o[2][1][1] = fmaf(p2, v1.y, o[2][1][1]);
            o[2][1][2] = fmaf(p2, v1.z, o[2][1][2]); o[2][1][3] = fmaf(p2, v1.w, o[2][1][3]);
            o[3][0][0] = fmaf(p3, v0.x, o[3][0][0]); o[3][0][1] = fmaf(p3, v0.y, o[3][0][1]);
            o[3][0][2] = fmaf(p3, v0.z, o[3][0][2]); o[3][0][3] = fmaf(p3, v0.w, o[3][0][3]);
            o[3][1][0] = fmaf(p3, v1.x, o[3][1][0]); o[3][1][1] = fmaf(p3, v1.y, o[3][1][1]);
            o[3][1][2] = fmaf(p3, v1.z, o[3][1][2]); o[3][1][3] = fmaf(p3, v1.w, o[3][1][3]);
        }
    }

    __syncthreads();
#pragma unroll
    for (int i = 0; i < 4; i++) {
        float inv = 1.0f / row_l[rg * 4 + i];
        size_t orow = ((size_t)(b * LSEQ + q0 + rg * 4 + i)) * DIMSZ + (size_t)h * HDIM;
        float4 a;
        a.x = o[i][0][0] * inv; a.y = o[i][0][1] * inv;
        a.z = o[i][0][2] * inv; a.w = o[i][0][3] * inv;
        *(float4*)&O[orow + cg * 4] = a;
        a.x = o[i][1][0] * inv; a.y = o[i][1][1] * inv;
        a.z = o[i][1][2] * inv; a.w = o[i][1][3] * inv;
        *(float4*)&O[orow + 64 + cg * 4] = a;
    }
}

// ---------------------------------------------------------------------------
extern "C" void kernel_launch(void* const* d_in, const int* in_sizes, int n_in,
                              void* d_out, int out_size)
{
    const float* x       = (const float*)d_in[0];
    const float* context = (const float*)d_in[1];
    const float* W_qkv   = (const float*)d_in[2];
    const float* b_qkv   = (const float*)d_in[3];
    const float* W_proj  = (const float*)d_in[4];
    const float* b_proj  = (const float*)d_in[5];
    float* out = (float*)d_out;

    float *qb, *kvb, *attnb;
    __nv_bfloat16 *xh, *xl, *ch, *cl, *wqh, *wql, *wph, *wpl, *ath, *atl;
    cudaGetSymbolAddress((void**)&qb,    g_q);
    cudaGetSymbolAddress((void**)&kvb,   g_kv);
    cudaGetSymbolAddress((void**)&attnb, g_attn);
    cudaGetSymbolAddress((void**)&xh,  g_xh);  cudaGetSymbolAddress((void**)&xl,  g_xl);
    cudaGetSymbolAddress((void**)&ch,  g_ch);  cudaGetSymbolAddress((void**)&cl,  g_cl);
    cudaGetSymbolAddress((void**)&wqh, g_wqh); cudaGetSymbolAddress((void**)&wql, g_wql);
    cudaGetSymbolAddress((void**)&wph, g_wph); cudaGetSymbolAddress((void**)&wpl, g_wpl);
    cudaGetSymbolAddress((void**)&ath, g_ath); cudaGetSymbolAddress((void**)&atl, g_atl);

    cudaFuncSetAttribute(gemm_mma, cudaFuncAttributeMaxDynamicSharedMemorySize, GEMM_SMEM);
    static const size_t att_smem = (size_t)ATT_SMEM_FLOATS * sizeof(float);
    cudaFuncSetAttribute(attn_kernel, cudaFuncAttributeMaxDynamicSharedMemorySize, (int)att_smem);

    const int n4 = MROWS * DIMSZ / 4;

    // 1) split inputs into bf16 hi/lo
    split_fp32<<<(n4 + 255) / 256, 256>>>(x, xh, xl, n4);
    split_fp32<<<(n4 + 255) / 256, 256>>>(context, ch, cl, n4);
    // 2) transpose+split weights
    transpose_split<<<dim3(3 * DIMSZ / 32, DIMSZ / 32), 256>>>(W_qkv, wqh, wql, DIMSZ, 3 * DIMSZ);
    transpose_split<<<dim3(DIMSZ / 32, DIMSZ / 32), 256>>>(W_proj, wph, wpl, DIMSZ, DIMSZ);

    // 3) fused qkv GEMM: N = 6144 (cols [0,2048)->q from x ; rest -> kv from context)
    gemm_mma<<<dim3(3 * DIMSZ / 128, MROWS / 128), 256, GEMM_SMEM>>>(
        xh, xl, ch, cl, wqh, wql, b_qkv,
        qb, DIMSZ, kvb, 2 * DIMSZ, DIMSZ);

    // 4) attention (fp32)
    attn_kernel<<<dim3(LSEQ / 64, NHEADS, BSZ), 256, att_smem>>>(qb, kvb, attnb);

    // 5) split attention output
    split_fp32<<<(n4 + 255) / 256, 256>>>(attnb, ath, atl, n4);

    // 6) output projection
    gemm_mma<<<dim3(DIMSZ / 128, MROWS / 128), 256, GEMM_SMEM>>>(
        ath, atl, ath, atl, wph, wpl, b_proj,
        out, DIMSZ, out, DIMSZ, 1 << 30);
}

// round 4
// speedup vs baseline: 2.2699x; 1.6444x over previous
#include <cuda_runtime.h>
#include <cuda_bf16.h>
#include <cstdint>

#define DIMSZ 2048
#define NHEADS 16
#define HDIM 128
#define BSZ 2
#define LSEQ 2048
#define MROWS (BSZ * LSEQ)   // 4096
#define KDIM 2048
#define SCALE_F 0.08838834764831845f

// ---------------------------------------------------------------------------
// Scratch (__device__ globals; no allocation allowed)
// ---------------------------------------------------------------------------
__device__ __nv_bfloat16 g_xh[(size_t)MROWS * DIMSZ];
__device__ __nv_bfloat16 g_xl[(size_t)MROWS * DIMSZ];
__device__ __nv_bfloat16 g_ch[(size_t)MROWS * DIMSZ];
__device__ __nv_bfloat16 g_cl[(size_t)MROWS * DIMSZ];
__device__ __nv_bfloat16 g_wqh[(size_t)3 * DIMSZ * DIMSZ];  // W_qkv^T [6144][2048]
__device__ __nv_bfloat16 g_wql[(size_t)3 * DIMSZ * DIMSZ];
__device__ __nv_bfloat16 g_wph[(size_t)DIMSZ * DIMSZ];      // W_proj^T [2048][2048]
__device__ __nv_bfloat16 g_wpl[(size_t)DIMSZ * DIMSZ];
__device__ __nv_bfloat16 g_qh[(size_t)MROWS * DIMSZ];       // q hi/lo
__device__ __nv_bfloat16 g_ql[(size_t)MROWS * DIMSZ];
__device__ __nv_bfloat16 g_kvh[(size_t)MROWS * 2 * DIMSZ];  // k|v hi/lo
__device__ __nv_bfloat16 g_kvl[(size_t)MROWS * 2 * DIMSZ];
__device__ __nv_bfloat16 g_ath[(size_t)MROWS * DIMSZ];      // attn out hi/lo
__device__ __nv_bfloat16 g_atl[(size_t)MROWS * DIMSZ];

// ---------------------------------------------------------------------------
// PTX helpers (baseline ISA: ldmatrix / mma.sync / cp.async)
// ---------------------------------------------------------------------------
__device__ __forceinline__ uint32_t smem_to_u32(const void* p) {
    uint32_t a;
    asm("{ .reg .u64 t; cvta.to.shared.u64 t, %1; cvt.u32.u64 %0, t; }" : "=r"(a) : "l"(p));
    return a;
}

#define CP_ASYNC16(dst, src) \
    asm volatile("cp.async.cg.shared.global [%0], [%1], 16;" :: "r"(dst), "l"(src) : "memory")
#define CP_COMMIT() asm volatile("cp.async.commit_group;" ::: "memory")
#define CP_WAIT(n)  asm volatile("cp.async.wait_group %0;" :: "n"(n) : "memory")

#define LDSM_X4(r0, r1, r2, r3, addr) \
    asm volatile("ldmatrix.sync.aligned.m8n8.x4.shared.b16 {%0,%1,%2,%3}, [%4];" \
                 : "=r"(r0), "=r"(r1), "=r"(r2), "=r"(r3) : "r"(addr))
#define LDSM_X4_T(r0, r1, r2, r3, addr) \
    asm volatile("ldmatrix.sync.aligned.m8n8.x4.trans.shared.b16 {%0,%1,%2,%3}, [%4];" \
                 : "=r"(r0), "=r"(r1), "=r"(r2), "=r"(r3) : "r"(addr))

#define MMA16816(d, a, b0, b1) \
    asm volatile("mma.sync.aligned.m16n8k16.row.col.f32.bf16.bf16.f32 " \
                 "{%0,%1,%2,%3}, {%4,%5,%6,%7}, {%8,%9}, {%0,%1,%2,%3};" \
                 : "+f"((d)[0]), "+f"((d)[1]), "+f"((d)[2]), "+f"((d)[3]) \
                 : "r"((a)[0]), "r"((a)[1]), "r"((a)[2]), "r"((a)[3]), \
                   "r"(b0), "r"(b1))

// pack two fp32 -> bf16x2 {hi:half1, lo:half0}
__device__ __forceinline__ uint32_t packbf(float lo, float hi) {
    uint32_t r;
    asm("cvt.rn.bf16x2.f32 %0, %1, %2;" : "=r"(r) : "f"(hi), "f"(lo));
    return r;
}
__device__ __forceinline__ float bflo_f(uint32_t u) { return __uint_as_float(u << 16); }
__device__ __forceinline__ float bfhi_f(uint32_t u) { return __uint_as_float(u & 0xffff0000u); }

// ---------------------------------------------------------------------------
// Conversion kernels
// ---------------------------------------------------------------------------
__global__ __launch_bounds__(256)
void split_fp32(const float* __restrict__ in, __nv_bfloat16* __restrict__ h,
                __nv_bfloat16* __restrict__ l, int n4)
{
    int i = blockIdx.x * 256 + threadIdx.x;
    if (i >= n4) return;
    float4 v = ((const float4*)in)[i];
    uint32_t h01 = packbf(v.x, v.y), h23 = packbf(v.z, v.w);
    uint32_t l01 = packbf(v.x - bflo_f(h01), v.y - bfhi_f(h01));
    uint32_t l23 = packbf(v.z - bflo_f(h23), v.w - bfhi_f(h23));
    ((uint32_t*)h)[2 * i] = h01; ((uint32_t*)h)[2 * i + 1] = h23;
    ((uint32_t*)l)[2 * i] = l01; ((uint32_t*)l)[2 * i + 1] = l23;
}

__global__ __launch_bounds__(256)
void transpose_split(const float* __restrict__ in, __nv_bfloat16* __restrict__ h,
                     __nv_bfloat16* __restrict__ l, int R, int C)
{
    __shared__ float tile[32][33];
    int c0 = blockIdx.x * 32, r0 = blockIdx.y * 32;
    int tx = threadIdx.x & 31, ty = threadIdx.x >> 5;
#pragma unroll
    for (int i = 0; i < 4; i++)
        tile[ty + 8 * i][tx] = in[(size_t)(r0 + ty + 8 * i) * C + c0 + tx];
    __syncthreads();
#pragma unroll
    for (int i = 0; i < 4; i++) {
        float v = tile[tx][ty + 8 * i];
        __nv_bfloat16 hv = __float2bfloat16(v);
        __nv_bfloat16 lv = __float2bfloat16(v - __bfloat162float(hv));
        size_t o = (size_t)(c0 + ty + 8 * i) * R + r0 + tx;
        h[o] = hv; l[o] = lv;
    }
}

// ---------------------------------------------------------------------------
// mma.sync split-bf16 GEMM: C = A @ B^T + bias (3 passes)
// outmode 0: fp32 C; outmode 1: bf16 hi/lo pair outputs
// ---------------------------------------------------------------------------
#define GBK 32
#define NCH (KDIM / GBK)
#define ROWB 80
#define TILE_B (128 * ROWB)
#define STAGE_B (4 * TILE_B)
#define GEMM_SMEM (2 * STAGE_B)

__global__ __launch_bounds__(256, 1)
void gemm_mma(const __nv_bfloat16* __restrict__ Ah0, const __nv_bfloat16* __restrict__ Al0,
              const __nv_bfloat16* __restrict__ Ah1, const __nv_bfloat16* __restrict__ Al1,
              const __nv_bfloat16* __restrict__ Bh, const __nv_bfloat16* __restrict__ Bl,
              const float* __restrict__ bias,
              float* __restrict__ Cf0, int ldc0, float* __restrict__ Cf1, int ldc1,
              __nv_bfloat16* __restrict__ Ch0, __nv_bfloat16* __restrict__ Cl0,
              __nv_bfloat16* __restrict__ Ch1, __nv_bfloat16* __restrict__ Cl1,
              int nsplit, int outmode)
{
    extern __shared__ char sm[];
    const uint32_t sbase = smem_to_u32(sm);
    const int tid  = threadIdx.x;
    const int lane = tid & 31;
    const int wid  = tid >> 5;
    const int wm   = (wid & 3) * 32;
    const int wn   = (wid >> 2) * 64;
    const int n0 = blockIdx.x * 128;
    const int m0 = blockIdx.y * 128;

    const __nv_bfloat16* Ah = (n0 < nsplit) ? Ah0 : Ah1;
    const __nv_bfloat16* Al = (n0 < nsplit) ? Al0 : Al1;

    float acc[2][8][4];
#pragma unroll
    for (int i = 0; i < 2; i++)
#pragma unroll
        for (int j = 0; j < 8; j++)
#pragma unroll
            for (int r = 0; r < 4; r++) acc[i][j][r] = 0.f;

    uint32_t aoff[2][2];
#pragma unroll
    for (int mf = 0; mf < 2; mf++)
#pragma unroll
        for (int ks = 0; ks < 2; ks++)
            aoff[mf][ks] = (uint32_t)((wm + mf * 16 + (lane & 15)) * ROWB
                                      + (ks * 16 + 8 * (lane >> 4)) * 2);
    uint32_t boff[4][2];
#pragma unroll
    for (int jj = 0; jj < 4; jj++)
#pragma unroll
        for (int ks = 0; ks < 2; ks++)
            boff[jj][ks] = (uint32_t)((wn + jj * 16 + (lane & 7) + 8 * (lane >> 4)) * ROWB
                                      + (ks * 16 + 8 * ((lane >> 3) & 1)) * 2);

    auto load_chunk = [&](int ic, int s) {
        const int k0 = ic * GBK;
#pragma unroll
        for (int it = 0; it < 8; it++) {
            const int tile   = it >> 1;
            const int within = (it & 1) * 256 + tid;
            const int row    = within >> 2;
            const int seg    = within & 3;
            const __nv_bfloat16* src;
            if (tile == 0)      src = Ah + (size_t)(m0 + row) * KDIM + k0 + seg * 8;
            else if (tile == 1) src = Al + (size_t)(m0 + row) * KDIM + k0 + seg * 8;
            else if (tile == 2) src = Bh + (size_t)(n0 + row) * KDIM + k0 + seg * 8;
            else                src = Bl + (size_t)(n0 + row) * KDIM + k0 + seg * 8;
            uint32_t dst = sbase + s * STAGE_B + tile * TILE_B + row * ROWB + seg * 16;
            CP_ASYNC16(dst, src);
        }
        CP_COMMIT();
    };

    load_chunk(0, 0);

    for (int ic = 0; ic < NCH; ic++) {
        const int s = ic & 1;
        if (ic + 1 < NCH) { load_chunk(ic + 1, s ^ 1); CP_WAIT(1); }
        else              { CP_WAIT(0); }
        __syncthreads();

        const uint32_t stage = sbase + s * STAGE_B;
#pragma unroll
        for (int pass = 0; pass < 3; pass++) {
            const uint32_t Abase = stage + ((pass == 2) ? TILE_B : 0);
            const uint32_t Bbase = stage + 2 * TILE_B + ((pass == 1) ? TILE_B : 0);
#pragma unroll
            for (int ks = 0; ks < 2; ks++) {
                uint32_t a[2][4];
                LDSM_X4(a[0][0], a[0][1], a[0][2], a[0][3], Abase + aoff[0][ks]);
                LDSM_X4(a[1][0], a[1][1], a[1][2], a[1][3], Abase + aoff[1][ks]);
#pragma unroll
                for (int jj = 0; jj < 4; jj++) {
                    uint32_t b0, b1, b2, b3;
                    LDSM_X4(b0, b1, b2, b3, Bbase + boff[jj][ks]);
                    MMA16816(acc[0][jj * 2],     a[0], b0, b1);
                    MMA16816(acc[1][jj * 2],     a[1], b0, b1);
                    MMA16816(acc[0][jj * 2 + 1], a[0], b2, b3);
                    MMA16816(acc[1][jj * 2 + 1], a[1], b2, b3);
                }
            }
        }
        __syncthreads();
    }

    // Epilogue
    int ld, nc0;
    float* Cf; __nv_bfloat16 *Ch, *Cl;
    if (n0 < nsplit) { Cf = Cf0; Ch = Ch0; Cl = Cl0; ld = ldc0; nc0 = n0; }
    else             { Cf = Cf1; Ch = Ch1; Cl = Cl1; ld = ldc1; nc0 = n0 - nsplit; }

#pragma unroll
    for (int mf = 0; mf < 2; mf++) {
#pragma unroll
        for (int nf = 0; nf < 8; nf++) {
            const int nl = wn + nf * 8 + 2 * (lane & 3);
            const float bx = bias[n0 + nl];
            const float by = bias[n0 + nl + 1];
            const int m_up = m0 + wm + mf * 16 + (lane >> 2);
#pragma unroll
            for (int half = 0; half < 2; half++) {
                const int m = m_up + 8 * half;
                float v0 = acc[mf][nf][2 * half]     + bx;
                float v1 = acc[mf][nf][2 * half + 1] + by;
                if (outmode == 0) {
                    float2 v; v.x = v0; v.y = v1;
                    *(float2*)(Cf + (size_t)m * ld + nc0 + nl) = v;
                } else {
                    uint32_t hi = packbf(v0, v1);
                    uint32_t lo = packbf(v0 - bflo_f(hi), v1 - bfhi_f(hi));
                    *(uint32_t*)(Ch + (size_t)m * ld + nc0 + nl) = hi;
                    *(uint32_t*)(Cl + (size_t)m * ld + nc0 + nl) = lo;
                }
            }
        }
    }
}

// ---------------------------------------------------------------------------
// Tensor-core flash attention (split-bf16, 3-pass QK and PV)
// CTA = (qtile of 128 rows, head, batch); 8 warps x 16-row warp tiles.
// ---------------------------------------------------------------------------
#define ASTR 272                         // smem row stride bytes (128 bf16 + pad)
#define Q_TILE (128 * ASTR)              // 34816
#define KV_TILE (64 * ASTR)              // 17408
#define KV_STAGE (4 * KV_TILE)           // 69632 : [Kh][Kl][Vh][Vl]
#define ATT_SMEM (2 * Q_TILE + 2 * KV_STAGE)   // 208896

__global__ __launch_bounds__(256, 1)
void attn_mma(const __nv_bfloat16* __restrict__ Qh, const __nv_bfloat16* __restrict__ Ql,
              const __nv_bfloat16* __restrict__ KVh, const __nv_bfloat16* __restrict__ KVl,
              __nv_bfloat16* __restrict__ Oh, __nv_bfloat16* __restrict__ Ol)
{
    extern __shared__ char sm[];
    const uint32_t sQh = smem_to_u32(sm);
    const uint32_t sQl = sQh + Q_TILE;
    const uint32_t sKV = sQl + Q_TILE;

    const int tid  = threadIdx.x;
    const int lane = tid & 31;
    const int wid  = tid >> 5;
    const int wm   = wid * 16;

    const int qt = blockIdx.x, h = blockIdx.y, b = blockIdx.z;
    const int qrow0 = b * LSEQ + qt * 128;
    const int hcol  = h * HDIM;

    // ---- load Q (hi+lo) ----
#pragma unroll
    for (int i = 0; i < 8; i++) {
        int idx = i * 256 + tid;
        int row = idx >> 4, seg = idx & 15;
        size_t g = (size_t)(qrow0 + row) * DIMSZ + hcol + seg * 8;
        uint32_t d = row * ASTR + seg * 16;
        CP_ASYNC16(sQh + d, Qh + g);
        CP_ASYNC16(sQl + d, Ql + g);
    }
    CP_COMMIT();

    auto load_kv = [&](int jt, int s) {
        const uint32_t base = sKV + s * KV_STAGE;
        const int krow0 = b * LSEQ + jt * 64;
#pragma unroll
        for (int i = 0; i < 4; i++) {
            int idx = i * 256 + tid;
            int row = idx >> 4, seg = idx & 15;
            size_t roff = (size_t)(krow0 + row) * (2 * DIMSZ);
            uint32_t d = row * ASTR + seg * 16;
            CP_ASYNC16(base + d,               KVh + roff + hcol + seg * 8);
            CP_ASYNC16(base + KV_TILE + d,     KVl + roff + hcol + seg * 8);
            CP_ASYNC16(base + 2 * KV_TILE + d, KVh + roff + DIMSZ + hcol + seg * 8);
            CP_ASYNC16(base + 3 * KV_TILE + d, KVl + roff + DIMSZ + hcol + seg * 8);
        }
        CP_COMMIT();
    };
    load_kv(0, 0);

    // per-thread ldmatrix base offsets
    const uint32_t ab = (uint32_t)((wm + (lane & 15)) * ASTR + (lane >> 4) * 16);
    const uint32_t kb = (uint32_t)(((lane & 7) + 8 * (lane >> 4)) * ASTR
                                   + ((lane >> 3) & 1) * 16);
    const uint32_t vb = (uint32_t)(((lane & 7) + 8 * ((lane >> 3) & 1)) * ASTR
                                   + (lane >> 4) * 16);

    float oacc[16][4];
#pragma unroll
    for (int f = 0; f < 16; f++)
#pragma unroll
        for (int e = 0; e < 4; e++) oacc[f][e] = 0.f;
    float m_prev[2] = {-3.0e38f, -3.0e38f};
    float l_acc[2]  = {0.f, 0.f};

    for (int jt = 0; jt < LSEQ / 64; jt++) {
        const int s = jt & 1;
        const bool has_next = (jt + 1 < LSEQ / 64);
        if (has_next) load_kv(jt + 1, s ^ 1);
        if (has_next) { CP_WAIT(1); } else { CP_WAIT(0); }
        __syncthreads();

        const uint32_t sK  = sKV + s * KV_STAGE;
        const uint32_t sKl = sK + KV_TILE;
        const uint32_t sV  = sK + 2 * KV_TILE;
        const uint32_t sVl = sK + 3 * KV_TILE;

        // ---- S = Q K^T (3 passes) ----
        float sacc[8][4];
#pragma unroll
        for (int f = 0; f < 8; f++)
#pragma unroll
            for (int e = 0; e < 4; e++) sacc[f][e] = 0.f;

#pragma unroll
        for (int ks = 0; ks < 8; ks++) {
            uint32_t ah[4], al[4];
            LDSM_X4(ah[0], ah[1], ah[2], ah[3], sQh + ab + ks * 32);
            LDSM_X4(al[0], al[1], al[2], al[3], sQl + ab + ks * 32);
#pragma unroll
            for (int jj = 0; jj < 4; jj++) {
                uint32_t h0, h1, h2, h3, l0, l1, l2, l3;
                LDSM_X4(h0, h1, h2, h3, sK  + kb + jj * (16 * ASTR) + ks * 32);
                LDSM_X4(l0, l1, l2, l3, sKl + kb + jj * (16 * ASTR) + ks * 32);
                MMA16816(sacc[2 * jj],     ah, h0, h1);
                MMA16816(sacc[2 * jj + 1], ah, h2, h3);
                MMA16816(sacc[2 * jj],     ah, l0, l1);
                MMA16816(sacc[2 * jj + 1], ah, l2, l3);
                MMA16816(sacc[2 * jj],     al, h0, h1);
                MMA16816(sacc[2 * jj + 1], al, h2, h3);
            }
        }

        // ---- online softmax (warp-local; rows r=lane>>2 and r+8) ----
        float mx0 = -3.0e38f, mx1 = -3.0e38f;
#pragma unroll
        for (int f = 0; f < 8; f++) {
            sacc[f][0] *= SCALE_F; sacc[f][1] *= SCALE_F;
            sacc[f][2] *= SCALE_F; sacc[f][3] *= SCALE_F;
            mx0 = fmaxf(mx0, fmaxf(sacc[f][0], sacc[f][1]));
            mx1 = fmaxf(mx1, fmaxf(sacc[f][2], sacc[f][3]));
        }
        mx0 = fmaxf(mx0, __shfl_xor_sync(0xffffffffu, mx0, 1));
        mx0 = fmaxf(mx0, __shfl_xor_sync(0xffffffffu, mx0, 2));
        mx1 = fmaxf(mx1, __shfl_xor_sync(0xffffffffu, mx1, 1));
        mx1 = fmaxf(mx1, __shfl_xor_sync(0xffffffffu, mx1, 2));

        float mnew0 = fmaxf(m_prev[0], mx0);
        float mnew1 = fmaxf(m_prev[1], mx1);
        float er0 = __expf(m_prev[0] - mnew0);
        float er1 = __expf(m_prev[1] - mnew1);
        m_prev[0] = mnew0; m_prev[1] = mnew1;

        float rsum0 = 0.f, rsum1 = 0.f;
#pragma unroll
        for (int f = 0; f < 8; f++) {
            sacc[f][0] = __expf(sacc[f][0] - mnew0);
            sacc[f][1] = __expf(sacc[f][1] - mnew0);
            sacc[f][2] = __expf(sacc[f][2] - mnew1);
            sacc[f][3] = __expf(sacc[f][3] - mnew1);
            rsum0 += sacc[f][0] + sacc[f][1];
            rsum1 += sacc[f][2] + sacc[f][3];
        }
        rsum0 += __shfl_xor_sync(0xffffffffu, rsum0, 1);
        rsum0 += __shfl_xor_sync(0xffffffffu, rsum0, 2);
        rsum1 += __shfl_xor_sync(0xffffffffu, rsum1, 1);
        rsum1 += __shfl_xor_sync(0xffffffffu, rsum1, 2);
        l_acc[0] = l_acc[0] * er0 + rsum0;
        l_acc[1] = l_acc[1] * er1 + rsum1;

#pragma unroll
        for (int f = 0; f < 16; f++) {
            oacc[f][0] *= er0; oacc[f][1] *= er0;
            oacc[f][2] *= er1; oacc[f][3] *= er1;
        }

        // ---- pack P into hi/lo A fragments ----
        uint32_t aph[4][4], apl[4][4];
#pragma unroll
        for (int t = 0; t < 4; t++) {
#pragma unroll
            for (int half = 0; half < 2; half++) {   // frag 2t / 2t+1 -> a0,a1 / a2,a3
                const int f = 2 * t + half;
                uint32_t u0 = packbf(sacc[f][0], sacc[f][1]);   // row r
                uint32_t u1 = packbf(sacc[f][2], sacc[f][3]);   // row r+8
                aph[t][2 * half]     = u0;
                aph[t][2 * half + 1] = u1;
                apl[t][2 * half] =
                    packbf(sacc[f][0] - bflo_f(u0), sacc[f][1] - bfhi_f(u0));
                apl[t][2 * half + 1] =
                    packbf(sacc[f][2] - bflo_f(u1), sacc[f][3] - bfhi_f(u1));
            }
        }

        // ---- O += P V (3 passes) ----
#pragma unroll
        for (int t = 0; t < 4; t++) {
#pragma unroll
            for (int g = 0; g < 8; g++) {
                uint32_t h0, h1, h2, h3, l0, l1, l2, l3;
                LDSM_X4_T(h0, h1, h2, h3, sV  + vb + t * (16 * ASTR) + g * 32);
                LDSM_X4_T(l0, l1, l2, l3, sVl + vb + t * (16 * ASTR) + g * 32);
                MMA16816(oacc[2 * g],     aph[t], h0, h1);
                MMA16816(oacc[2 * g + 1], aph[t], h2, h3);
                MMA16816(oacc[2 * g],     aph[t], l0, l1);
                MMA16816(oacc[2 * g + 1], aph[t], l2, l3);
                MMA16816(oacc[2 * g],     apl[t], h0, h1);
                MMA16816(oacc[2 * g + 1], apl[t], h2, h3);
            }
        }
        __syncthreads();
    }

    // ---- epilogue: normalize, split to bf16 hi/lo ----
#pragma unroll
    for (int rs = 0; rs < 2; rs++) {
        const float inv = 1.0f / l_acc[rs];
        const int row = qrow0 + wm + (lane >> 2) + 8 * rs;
#pragma unroll
        for (int f = 0; f < 16; f++) {
            float v0 = oacc[f][2 * rs]     * inv;
            float v1 = oacc[f][2 * rs + 1] * inv;
            uint32_t hi = packbf(v0, v1);
            uint32_t lo = packbf(v0 - bflo_f(hi), v1 - bfhi_f(hi));
            const int col = hcol + f * 8 + 2 * (lane & 3);
            *(uint32_t*)(Oh + (size_t)row * DIMSZ + col) = hi;
            *(uint32_t*)(Ol + (size_t)row * DIMSZ + col) = lo;
        }
    }
}

// ---------------------------------------------------------------------------
extern "C" void kernel_launch(void* const* d_in, const int* in_sizes, int n_in,
                              void* d_out, int out_size)
{
    const float* x       = (const float*)d_in[0];
    const float* context = (const float*)d_in[1];
    const float* W_qkv   = (const float*)d_in[2];
    const float* b_qkv   = (const float*)d_in[3];
    const float* W_proj  = (const float*)d_in[4];
    const float* b_proj  = (const float*)d_in[5];
    float* out = (float*)d_out;

    __nv_bfloat16 *xh, *xl, *ch, *cl, *wqh, *wql, *wph, *wpl;
    __nv_bfloat16 *qh, *ql, *kvh, *kvl, *ath, *atl;
    cudaGetSymbolAddress((void**)&xh,  g_xh);  cudaGetSymbolAddress((void**)&xl,  g_xl);
    cudaGetSymbolAddress((void**)&ch,  g_ch);  cudaGetSymbolAddress((void**)&cl,  g_cl);
    cudaGetSymbolAddress((void**)&wqh, g_wqh); cudaGetSymbolAddress((void**)&wql, g_wql);
    cudaGetSymbolAddress((void**)&wph, g_wph); cudaGetSymbolAddress((void**)&wpl, g_wpl);
    cudaGetSymbolAddress((void**)&qh,  g_qh);  cudaGetSymbolAddress((void**)&ql,  g_ql);
    cudaGetSymbolAddress((void**)&kvh, g_kvh); cudaGetSymbolAddress((void**)&kvl, g_kvl);
    cudaGetSymbolAddress((void**)&ath, g_ath); cudaGetSymbolAddress((void**)&atl, g_atl);

    cudaFuncSetAttribute(gemm_mma, cudaFuncAttributeMaxDynamicSharedMemorySize, GEMM_SMEM);
    cudaFuncSetAttribute(attn_mma, cudaFuncAttributeMaxDynamicSharedMemorySize, ATT_SMEM);

    const int n4 = MROWS * DIMSZ / 4;

    // 1) split inputs
    split_fp32<<<(n4 + 255) / 256, 256>>>(x, xh, xl, n4);
    split_fp32<<<(n4 + 255) / 256, 256>>>(context, ch, cl, n4);
    // 2) transpose+split weights
    transpose_split<<<dim3(3 * DIMSZ / 32, DIMSZ / 32), 256>>>(W_qkv, wqh, wql, DIMSZ, 3 * DIMSZ);
    transpose_split<<<dim3(DIMSZ / 32, DIMSZ / 32), 256>>>(W_proj, wph, wpl, DIMSZ, DIMSZ);

    // 3) fused qkv GEMM (bf16 hi/lo outputs): q [4096][2048], kv [4096][4096]
    gemm_mma<<<dim3(3 * DIMSZ / 128, MROWS / 128), 256, GEMM_SMEM>>>(
        xh, xl, ch, cl, wqh, wql, b_qkv,
        nullptr, DIMSZ, nullptr, 2 * DIMSZ,
        qh, ql, kvh, kvl, DIMSZ, 1);

    // 4) tensor-core attention -> bf16 hi/lo
    attn_mma<<<dim3(LSEQ / 128, NHEADS, BSZ), 256, ATT_SMEM>>>(qh, ql, kvh, kvl, ath, atl);

    // 5) output projection (fp32 out)
    gemm_mma<<<dim3(DIMSZ / 128, MROWS / 128), 256, GEMM_SMEM>>>(
        ath, atl, ath, atl, wph, wpl, b_proj,
        out, DIMSZ, out, DIMSZ,
        nullptr, nullptr, nullptr, nullptr, 1 << 30, 0);
}

// round 5
// speedup vs baseline: 2.4853x; 1.0949x over previous
#include <cuda_runtime.h>
#include <cuda_bf16.h>
#include <cstdint>

#define DIMSZ 2048
#define NHEADS 16
#define HDIM 128
#define BSZ 2
#define LSEQ 2048
#define MROWS (BSZ * LSEQ)   // 4096
#define KDIM 2048
#define SCALE_F 0.08838834764831845f

// ---------------------------------------------------------------------------
// Scratch (__device__ globals; no allocation allowed)
// ---------------------------------------------------------------------------
__device__ __nv_bfloat16 g_xh[(size_t)MROWS * DIMSZ];
__device__ __nv_bfloat16 g_xl[(size_t)MROWS * DIMSZ];
__device__ __nv_bfloat16 g_ch[(size_t)MROWS * DIMSZ];
__device__ __nv_bfloat16 g_cl[(size_t)MROWS * DIMSZ];
__device__ __nv_bfloat16 g_wqh[(size_t)3 * DIMSZ * DIMSZ];  // W_qkv^T [6144][2048]
__device__ __nv_bfloat16 g_wql[(size_t)3 * DIMSZ * DIMSZ];
__device__ __nv_bfloat16 g_wph[(size_t)DIMSZ * DIMSZ];      // W_proj^T [2048][2048]
__device__ __nv_bfloat16 g_wpl[(size_t)DIMSZ * DIMSZ];
__device__ __nv_bfloat16 g_qh[(size_t)MROWS * DIMSZ];
__device__ __nv_bfloat16 g_ql[(size_t)MROWS * DIMSZ];
__device__ __nv_bfloat16 g_kvh[(size_t)MROWS * 2 * DIMSZ];
__device__ __nv_bfloat16 g_kvl[(size_t)MROWS * 2 * DIMSZ];
__device__ __nv_bfloat16 g_ath[(size_t)MROWS * DIMSZ];
__device__ __nv_bfloat16 g_atl[(size_t)MROWS * DIMSZ];

// ---------------------------------------------------------------------------
// PTX helpers (baseline ISA: ldmatrix / mma.sync / cp.async)
// ---------------------------------------------------------------------------
__device__ __forceinline__ uint32_t smem_to_u32(const void* p) {
    uint32_t a;
    asm("{ .reg .u64 t; cvta.to.shared.u64 t, %1; cvt.u32.u64 %0, t; }" : "=r"(a) : "l"(p));
    return a;
}

#define CP_ASYNC16(dst, src) \
    asm volatile("cp.async.cg.shared.global [%0], [%1], 16;" :: "r"(dst), "l"(src) : "memory")
#define CP_COMMIT() asm volatile("cp.async.commit_group;" ::: "memory")
#define CP_WAIT(n)  asm volatile("cp.async.wait_group %0;" :: "n"(n) : "memory")

#define LDSM_X4(r0, r1, r2, r3, addr) \
    asm volatile("ldmatrix.sync.aligned.m8n8.x4.shared.b16 {%0,%1,%2,%3}, [%4];" \
                 : "=r"(r0), "=r"(r1), "=r"(r2), "=r"(r3) : "r"(addr))
#define LDSM_X4_T(r0, r1, r2, r3, addr) \
    asm volatile("ldmatrix.sync.aligned.m8n8.x4.trans.shared.b16 {%0,%1,%2,%3}, [%4];" \
                 : "=r"(r0), "=r"(r1), "=r"(r2), "=r"(r3) : "r"(addr))

#define MMA16816(d, a, b0, b1) \
    asm volatile("mma.sync.aligned.m16n8k16.row.col.f32.bf16.bf16.f32 " \
                 "{%0,%1,%2,%3}, {%4,%5,%6,%7}, {%8,%9}, {%0,%1,%2,%3};" \
                 : "+f"((d)[0]), "+f"((d)[1]), "+f"((d)[2]), "+f"((d)[3]) \
                 : "r"((a)[0]), "r"((a)[1]), "r"((a)[2]), "r"((a)[3]), \
                   "r"(b0), "r"(b1))

__device__ __forceinline__ uint32_t packbf(float lo, float hi) {
    uint32_t r;
    asm("cvt.rn.bf16x2.f32 %0, %1, %2;" : "=r"(r) : "f"(hi), "f"(lo));
    return r;
}
__device__ __forceinline__ float bflo_f(uint32_t u) { return __uint_as_float(u << 16); }
__device__ __forceinline__ float bfhi_f(uint32_t u) { return __uint_as_float(u & 0xffff0000u); }

// ---------------------------------------------------------------------------
// Conversion kernels
// ---------------------------------------------------------------------------
__global__ __launch_bounds__(256)
void split_fp32(const float* __restrict__ in, __nv_bfloat16* __restrict__ h,
                __nv_bfloat16* __restrict__ l, int n4)
{
    int i = blockIdx.x * 256 + threadIdx.x;
    if (i >= n4) return;
    float4 v = ((const float4*)in)[i];
    uint32_t h01 = packbf(v.x, v.y), h23 = packbf(v.z, v.w);
    uint32_t l01 = packbf(v.x - bflo_f(h01), v.y - bfhi_f(h01));
    uint32_t l23 = packbf(v.z - bflo_f(h23), v.w - bfhi_f(h23));
    ((uint32_t*)h)[2 * i] = h01; ((uint32_t*)h)[2 * i + 1] = h23;
    ((uint32_t*)l)[2 * i] = l01; ((uint32_t*)l)[2 * i + 1] = l23;
}

__global__ __launch_bounds__(256)
void transpose_split(const float* __restrict__ in, __nv_bfloat16* __restrict__ h,
                     __nv_bfloat16* __restrict__ l, int R, int C)
{
    __shared__ float tile[32][33];
    int c0 = blockIdx.x * 32, r0 = blockIdx.y * 32;
    int tx = threadIdx.x & 31, ty = threadIdx.x >> 5;
#pragma unroll
    for (int i = 0; i < 4; i++)
        tile[ty + 8 * i][tx] = in[(size_t)(r0 + ty + 8 * i) * C + c0 + tx];
    __syncthreads();
#pragma unroll
    for (int i = 0; i < 4; i++) {
        float v = tile[tx][ty + 8 * i];
        __nv_bfloat16 hv = __float2bfloat16(v);
        __nv_bfloat16 lv = __float2bfloat16(v - __bfloat162float(hv));
        size_t o = (size_t)(c0 + ty + 8 * i) * R + r0 + tx;
        h[o] = hv; l[o] = lv;
    }
}

// ---------------------------------------------------------------------------
// mma.sync split-bf16 GEMM: C = A @ B^T + bias (3 passes)
// CTA 256x128x32, 8 warps (warp tile 64m x 64n), 3-stage cp.async pipeline.
// outmode 0: fp32 C; outmode 1: bf16 hi/lo pair outputs
// ---------------------------------------------------------------------------
#define GBM 256
#define GBN 128
#define GBK 32
#define NCH (KDIM / GBK)         // 64
#define ROWB 80
#define ATB (GBM * ROWB)         // 20480
#define BTB (GBN * ROWB)         // 10240
#define STB (2 * ATB + 2 * BTB)  // 61440 : [Ah][Al][Bh][Bl]
#define NSTAGE 3
#define GEMM_SMEM (NSTAGE * STB) // 184320

__global__ __launch_bounds__(256, 1)
void gemm_mma(const __nv_bfloat16* __restrict__ Ah0, const __nv_bfloat16* __restrict__ Al0,
              const __nv_bfloat16* __restrict__ Ah1, const __nv_bfloat16* __restrict__ Al1,
              const __nv_bfloat16* __restrict__ Bh, const __nv_bfloat16* __restrict__ Bl,
              const float* __restrict__ bias,
              float* __restrict__ Cf0, int ldc0, float* __restrict__ Cf1, int ldc1,
              __nv_bfloat16* __restrict__ Ch0, __nv_bfloat16* __restrict__ Cl0,
              __nv_bfloat16* __restrict__ Ch1, __nv_bfloat16* __restrict__ Cl1,
              int nsplit, int outmode)
{
    extern __shared__ char sm[];
    const uint32_t sbase = smem_to_u32(sm);
    const int tid  = threadIdx.x;
    const int lane = tid & 31;
    const int wid  = tid >> 5;
    const int wm   = (wid & 3) * 64;
    const int wn   = (wid >> 2) * 64;
    const int n0 = blockIdx.x * GBN;
    const int m0 = blockIdx.y * GBM;

    const __nv_bfloat16* Ah = (n0 < nsplit) ? Ah0 : Ah1;
    const __nv_bfloat16* Al = (n0 < nsplit) ? Al0 : Al1;

    float acc[4][8][4];
#pragma unroll
    for (int i = 0; i < 4; i++)
#pragma unroll
        for (int j = 0; j < 8; j++)
#pragma unroll
            for (int r = 0; r < 4; r++) acc[i][j][r] = 0.f;

    uint32_t aoff[4];
#pragma unroll
    for (int mf = 0; mf < 4; mf++)
        aoff[mf] = (uint32_t)((wm + mf * 16 + (lane & 15)) * ROWB + (lane >> 4) * 16);
    uint32_t boff[4];
#pragma unroll
    for (int jj = 0; jj < 4; jj++)
        boff[jj] = (uint32_t)((wn + jj * 16 + (lane & 7) + 8 * (lane >> 4)) * ROWB
                              + ((lane >> 3) & 1) * 16);

    auto load_chunk = [&](int ic, int s) {
        const int k0 = ic * GBK;
        const uint32_t stage = sbase + s * STB;
        // A hi/lo: 256 rows x 4 segs
#pragma unroll
        for (int it = 0; it < 4; it++) {
            const int idx = it * 256 + tid;
            const int row = idx >> 2, seg = idx & 3;
            const size_t g = (size_t)(m0 + row) * KDIM + k0 + seg * 8;
            const uint32_t dst = stage + row * ROWB + seg * 16;
            CP_ASYNC16(dst, Ah + g);
            CP_ASYNC16(dst + ATB, Al + g);
        }
        // B hi/lo: 128 rows x 4 segs
#pragma unroll
        for (int it = 0; it < 2; it++) {
            const int idx = it * 256 + tid;
            const int row = idx >> 2, seg = idx & 3;
            const size_t g = (size_t)(n0 + row) * KDIM + k0 + seg * 8;
            const uint32_t dst = stage + 2 * ATB + row * ROWB + seg * 16;
            CP_ASYNC16(dst, Bh + g);
            CP_ASYNC16(dst + BTB, Bl + g);
        }
        CP_COMMIT();
    };

    load_chunk(0, 0);
    load_chunk(1, 1);

    for (int ic = 0; ic < NCH; ic++) {
        const int s = ic % NSTAGE;
        if (ic + 2 < NCH)      { load_chunk(ic + 2, (ic + 2) % NSTAGE); CP_WAIT(2); }
        else if (ic + 1 < NCH) { CP_WAIT(1); }
        else                   { CP_WAIT(0); }
        __syncthreads();

        const uint32_t sA = sbase + s * STB;
        const uint32_t sB = sA + 2 * ATB;
#pragma unroll
        for (int ks = 0; ks < 2; ks++) {
            uint32_t ah[4][4], al[4][4];
#pragma unroll
            for (int mf = 0; mf < 4; mf++) {
                LDSM_X4(ah[mf][0], ah[mf][1], ah[mf][2], ah[mf][3], sA + aoff[mf] + ks * 32);
                LDSM_X4(al[mf][0], al[mf][1], al[mf][2], al[mf][3], sA + ATB + aoff[mf] + ks * 32);
            }
#pragma unroll
            for (int jj = 0; jj < 4; jj++) {
                uint32_t bh0, bh1, bh2, bh3, bl0, bl1, bl2, bl3;
                LDSM_X4(bh0, bh1, bh2, bh3, sB + boff[jj] + ks * 32);
                LDSM_X4(bl0, bl1, bl2, bl3, sB + BTB + boff[jj] + ks * 32);
#pragma unroll
                for (int mf = 0; mf < 4; mf++) {
                    MMA16816(acc[mf][2 * jj],     ah[mf], bh0, bh1);
                    MMA16816(acc[mf][2 * jj + 1], ah[mf], bh2, bh3);
                    MMA16816(acc[mf][2 * jj],     ah[mf], bl0, bl1);
                    MMA16816(acc[mf][2 * jj + 1], ah[mf], bl2, bl3);
                    MMA16816(acc[mf][2 * jj],     al[mf], bh0, bh1);
                    MMA16816(acc[mf][2 * jj + 1], al[mf], bh2, bh3);
                }
            }
        }
        __syncthreads();
    }

    // Epilogue
    int ld, nc0;
    float* Cf; __nv_bfloat16 *Ch, *Cl;
    if (n0 < nsplit) { Cf = Cf0; Ch = Ch0; Cl = Cl0; ld = ldc0; nc0 = n0; }
    else             { Cf = Cf1; Ch = Ch1; Cl = Cl1; ld = ldc1; nc0 = n0 - nsplit; }

#pragma unroll
    for (int mf = 0; mf < 4; mf++) {
#pragma unroll
        for (int nf = 0; nf < 8; nf++) {
            const int nl = wn + nf * 8 + 2 * (lane & 3);
            const float bx = bias[n0 + nl];
            const float by = bias[n0 + nl + 1];
            const int m_up = m0 + wm + mf * 16 + (lane >> 2);
#pragma unroll
            for (int half = 0; half < 2; half++) {
                const int m = m_up + 8 * half;
                float v0 = acc[mf][nf][2 * half]     + bx;
                float v1 = acc[mf][nf][2 * half + 1] + by;
                if (outmode == 0) {
                    float2 v; v.x = v0; v.y = v1;
                    *(float2*)(Cf + (size_t)m * ld + nc0 + nl) = v;
                } else {
                    uint32_t hi = packbf(v0, v1);
                    uint32_t lo = packbf(v0 - bflo_f(hi), v1 - bfhi_f(hi));
                    *(uint32_t*)(Ch + (size_t)m * ld + nc0 + nl) = hi;
                    *(uint32_t*)(Cl + (size_t)m * ld + nc0 + nl) = lo;
                }
            }
        }
    }
}

// ---------------------------------------------------------------------------
// Tensor-core flash attention (split-bf16, 3-pass QK and PV) — unchanged R4
// ---------------------------------------------------------------------------
#define ASTR 272
#define Q_TILE (128 * ASTR)
#define KV_TILE (64 * ASTR)
#define KV_STAGE (4 * KV_TILE)
#define ATT_SMEM (2 * Q_TILE + 2 * KV_STAGE)

__global__ __launch_bounds__(256, 1)
void attn_mma(const __nv_bfloat16* __restrict__ Qh, const __nv_bfloat16* __restrict__ Ql,
              const __nv_bfloat16* __restrict__ KVh, const __nv_bfloat16* __restrict__ KVl,
              __nv_bfloat16* __restrict__ Oh, __nv_bfloat16* __restrict__ Ol)
{
    extern __shared__ char sm[];
    const uint32_t sQh = smem_to_u32(sm);
    const uint32_t sQl = sQh + Q_TILE;
    const uint32_t sKV = sQl + Q_TILE;

    const int tid  = threadIdx.x;
    const int lane = tid & 31;
    const int wid  = tid >> 5;
    const int wm   = wid * 16;

    const int qt = blockIdx.x, h = blockIdx.y, b = blockIdx.z;
    const int qrow0 = b * LSEQ + qt * 128;
    const int hcol  = h * HDIM;

#pragma unroll
    for (int i = 0; i < 8; i++) {
        int idx = i * 256 + tid;
        int row = idx >> 4, seg = idx & 15;
        size_t g = (size_t)(qrow0 + row) * DIMSZ + hcol + seg * 8;
        uint32_t d = row * ASTR + seg * 16;
        CP_ASYNC16(sQh + d, Qh + g);
        CP_ASYNC16(sQl + d, Ql + g);
    }
    CP_COMMIT();

    auto load_kv = [&](int jt, int s) {
        const uint32_t base = sKV + s * KV_STAGE;
        const int krow0 = b * LSEQ + jt * 64;
#pragma unroll
        for (int i = 0; i < 4; i++) {
            int idx = i * 256 + tid;
            int row = idx >> 4, seg = idx & 15;
            size_t roff = (size_t)(krow0 + row) * (2 * DIMSZ);
            uint32_t d = row * ASTR + seg * 16;
            CP_ASYNC16(base + d,               KVh + roff + hcol + seg * 8);
            CP_ASYNC16(base + KV_TILE + d,     KVl + roff + hcol + seg * 8);
            CP_ASYNC16(base + 2 * KV_TILE + d, KVh + roff + DIMSZ + hcol + seg * 8);
            CP_ASYNC16(base + 3 * KV_TILE + d, KVl + roff + DIMSZ + hcol + seg * 8);
        }
        CP_COMMIT();
    };
    load_kv(0, 0);

    const uint32_t ab = (uint32_t)((wm + (lane & 15)) * ASTR + (lane >> 4) * 16);
    const uint32_t kb = (uint32_t)(((lane & 7) + 8 * (lane >> 4)) * ASTR
                                   + ((lane >> 3) & 1) * 16);
    const uint32_t vb = (uint32_t)(((lane & 7) + 8 * ((lane >> 3) & 1)) * ASTR
                                   + (lane >> 4) * 16);

    float oacc[16][4];
#pragma unroll
    for (int f = 0; f < 16; f++)
#pragma unroll
        for (int e = 0; e < 4; e++) oacc[f][e] = 0.f;
    float m_prev[2] = {-3.0e38f, -3.0e38f};
    float l_acc[2]  = {0.f, 0.f};

    for (int jt = 0; jt < LSEQ / 64; jt++) {
        const int s = jt & 1;
        const bool has_next = (jt + 1 < LSEQ / 64);
        if (has_next) load_kv(jt + 1, s ^ 1);
        if (has_next) { CP_WAIT(1); } else { CP_WAIT(0); }
        __syncthreads();

        const uint32_t sK  = sKV + s * KV_STAGE;
        const uint32_t sKl = sK + KV_TILE;
        const uint32_t sV  = sK + 2 * KV_TILE;
        const uint32_t sVl = sK + 3 * KV_TILE;

        float sacc[8][4];
#pragma unroll
        for (int f = 0; f < 8; f++)
#pragma unroll
            for (int e = 0; e < 4; e++) sacc[f][e] = 0.f;

#pragma unroll
        for (int ks = 0; ks < 8; ks++) {
            uint32_t ah[4], al[4];
            LDSM_X4(ah[0], ah[1], ah[2], ah[3], sQh + ab + ks * 32);
            LDSM_X4(al[0], al[1], al[2], al[3], sQl + ab + ks * 32);
#pragma unroll
            for (int jj = 0; jj < 4; jj++) {
                uint32_t h0, h1, h2, h3, l0, l1, l2, l3;
                LDSM_X4(h0, h1, h2, h3, sK  + kb + jj * (16 * ASTR) + ks * 32);
                LDSM_X4(l0, l1, l2, l3, sKl + kb + jj * (16 * ASTR) + ks * 32);
                MMA16816(sacc[2 * jj],     ah, h0, h1);
                MMA16816(sacc[2 * jj + 1], ah, h2, h3);
                MMA16816(sacc[2 * jj],     ah, l0, l1);
                MMA16816(sacc[2 * jj + 1], ah, l2, l3);
                MMA16816(sacc[2 * jj],     al, h0, h1);
                MMA16816(sacc[2 * jj + 1], al, h2, h3);
            }
        }

        float mx0 = -3.0e38f, mx1 = -3.0e38f;
#pragma unroll
        for (int f = 0; f < 8; f++) {
            sacc[f][0] *= SCALE_F; sacc[f][1] *= SCALE_F;
            sacc[f][2] *= SCALE_F; sacc[f][3] *= SCALE_F;
            mx0 = fmaxf(mx0, fmaxf(sacc[f][0], sacc[f][1]));
            mx1 = fmaxf(mx1, fmaxf(sacc[f][2], sacc[f][3]));
        }
        mx0 = fmaxf(mx0, __shfl_xor_sync(0xffffffffu, mx0, 1));
        mx0 = fmaxf(mx0, __shfl_xor_sync(0xffffffffu, mx0, 2));
        mx1 = fmaxf(mx1, __shfl_xor_sync(0xffffffffu, mx1, 1));
        mx1 = fmaxf(mx1, __shfl_xor_sync(0xffffffffu, mx1, 2));

        float mnew0 = fmaxf(m_prev[0], mx0);
        float mnew1 = fmaxf(m_prev[1], mx1);
        float er0 = __expf(m_prev[0] - mnew0);
        float er1 = __expf(m_prev[1] - mnew1);
        m_prev[0] = mnew0; m_prev[1] = mnew1;

        float rsum0 = 0.f, rsum1 = 0.f;
#pragma unroll
        for (int f = 0; f < 8; f++) {
            sacc[f][0] = __expf(sacc[f][0] - mnew0);
            sacc[f][1] = __expf(sacc[f][1] - mnew0);
            sacc[f][2] = __expf(sacc[f][2] - mnew1);
            sacc[f][3] = __expf(sacc[f][3] - mnew1);
            rsum0 += sacc[f][0] + sacc[f][1];
            rsum1 += sacc[f][2] + sacc[f][3];
        }
        rsum0 += __shfl_xor_sync(0xffffffffu, rsum0, 1);
        rsum0 += __shfl_xor_sync(0xffffffffu, rsum0, 2);
        rsum1 += __shfl_xor_sync(0xffffffffu, rsum1, 1);
        rsum1 += __shfl_xor_sync(0xffffffffu, rsum1, 2);
        l_acc[0] = l_acc[0] * er0 + rsum0;
        l_acc[1] = l_acc[1] * er1 + rsum1;

#pragma unroll
        for (int f = 0; f < 16; f++) {
            oacc[f][0] *= er0; oacc[f][1] *= er0;
            oacc[f][2] *= er1; oacc[f][3] *= er1;
        }

        uint32_t aph[4][4], apl[4][4];
#pragma unroll
        for (int t = 0; t < 4; t++) {
#pragma unroll
            for (int half = 0; half < 2; half++) {
                const int f = 2 * t + half;
                uint32_t u0 = packbf(sacc[f][0], sacc[f][1]);
                uint32_t u1 = packbf(sacc[f][2], sacc[f][3]);
                aph[t][2 * half]     = u0;
                aph[t][2 * half + 1] = u1;
                apl[t][2 * half] =
                    packbf(sacc[f][0] - bflo_f(u0), sacc[f][1] - bfhi_f(u0));
                apl[t][2 * half + 1] =
                    packbf(sacc[f][2] - bflo_f(u1), sacc[f][3] - bfhi_f(u1));
            }
        }

#pragma unroll
        for (int t = 0; t < 4; t++) {
#pragma unroll
            for (int g = 0; g < 8; g++) {
                uint32_t h0, h1, h2, h3, l0, l1, l2, l3;
                LDSM_X4_T(h0, h1, h2, h3, sV  + vb + t * (16 * ASTR) + g * 32);
                LDSM_X4_T(l0, l1, l2, l3, sVl + vb + t * (16 * ASTR) + g * 32);
                MMA16816(oacc[2 * g],     aph[t], h0, h1);
                MMA16816(oacc[2 * g + 1], aph[t], h2, h3);
                MMA16816(oacc[2 * g],     aph[t], l0, l1);
                MMA16816(oacc[2 * g + 1], aph[t], l2, l3);
                MMA16816(oacc[2 * g],     apl[t], h0, h1);
                MMA16816(oacc[2 * g + 1], apl[t], h2, h3);
            }
        }
        __syncthreads();
    }

#pragma unroll
    for (int rs = 0; rs < 2; rs++) {
        const float inv = 1.0f / l_acc[rs];
        const int row = qrow0 + wm + (lane >> 2) + 8 * rs;
#pragma unroll
        for (int f = 0; f < 16; f++) {
            float v0 = oacc[f][2 * rs]     * inv;
            float v1 = oacc[f][2 * rs + 1] * inv;
            uint32_t hi = packbf(v0, v1);
            uint32_t lo = packbf(v0 - bflo_f(hi), v1 - bfhi_f(hi));
            const int col = hcol + f * 8 + 2 * (lane & 3);
            *(uint32_t*)(Oh + (size_t)row * DIMSZ + col) = hi;
            *(uint32_t*)(Ol + (size_t)row * DIMSZ + col) = lo;
        }
    }
}

// ---------------------------------------------------------------------------
extern "C" void kernel_launch(void* const* d_in, const int* in_sizes, int n_in,
                              void* d_out, int out_size)
{
    const float* x       = (const float*)d_in[0];
    const float* context = (const float*)d_in[1];
    const float* W_qkv   = (const float*)d_in[2];
    const float* b_qkv   = (const float*)d_in[3];
    const float* W_proj  = (const float*)d_in[4];
    const float* b_proj  = (const float*)d_in[5];
    float* out = (float*)d_out;

    __nv_bfloat16 *xh, *xl, *ch, *cl, *wqh, *wql, *wph, *wpl;
    __nv_bfloat16 *qh, *ql, *kvh, *kvl, *ath, *atl;
    cudaGetSymbolAddress((void**)&xh,  g_xh);  cudaGetSymbolAddress((void**)&xl,  g_xl);
    cudaGetSymbolAddress((void**)&ch,  g_ch);  cudaGetSymbolAddress((void**)&cl,  g_cl);
    cudaGetSymbolAddress((void**)&wqh, g_wqh); cudaGetSymbolAddress((void**)&wql, g_wql);
    cudaGetSymbolAddress((void**)&wph, g_wph); cudaGetSymbolAddress((void**)&wpl, g_wpl);
    cudaGetSymbolAddress((void**)&qh,  g_qh);  cudaGetSymbolAddress((void**)&ql,  g_ql);
    cudaGetSymbolAddress((void**)&kvh, g_kvh); cudaGetSymbolAddress((void**)&kvl, g_kvl);
    cudaGetSymbolAddress((void**)&ath, g_ath); cudaGetSymbolAddress((void**)&atl, g_atl);

    cudaFuncSetAttribute(gemm_mma, cudaFuncAttributeMaxDynamicSharedMemorySize, GEMM_SMEM);
    cudaFuncSetAttribute(attn_mma, cudaFuncAttributeMaxDynamicSharedMemorySize, ATT_SMEM);

    const int n4 = MROWS * DIMSZ / 4;

    split_fp32<<<(n4 + 255) / 256, 256>>>(x, xh, xl, n4);
    split_fp32<<<(n4 + 255) / 256, 256>>>(context, ch, cl, n4);
    transpose_split<<<dim3(3 * DIMSZ / 32, DIMSZ / 32), 256>>>(W_qkv, wqh, wql, DIMSZ, 3 * DIMSZ);
    transpose_split<<<dim3(DIMSZ / 32, DIMSZ / 32), 256>>>(W_proj, wph, wpl, DIMSZ, DIMSZ);

    gemm_mma<<<dim3(3 * DIMSZ / GBN, MROWS / GBM), 256, GEMM_SMEM>>>(
        xh, xl, ch, cl, wqh, wql, b_qkv,
        nullptr, DIMSZ, nullptr, 2 * DIMSZ,
        qh, ql, kvh, kvl, DIMSZ, 1);

    attn_mma<<<dim3(LSEQ / 128, NHEADS, BSZ), 256, ATT_SMEM>>>(qh, ql, kvh, kvl, ath, atl);

    gemm_mma<<<dim3(DIMSZ / GBN, MROWS / GBM), 256, GEMM_SMEM>>>(
        ath, atl, ath, atl, wph, wpl, b_proj,
        out, DIMSZ, out, DIMSZ,
        nullptr, nullptr, nullptr, nullptr, 1 << 30, 0);
}

// round 6
// speedup vs baseline: 2.4930x; 1.0031x over previous
#include <cuda_runtime.h>
#include <cuda_bf16.h>
#include <cstdint>

#define DIMSZ 2048
#define NHEADS 16
#define HDIM 128
#define BSZ 2
#define LSEQ 2048
#define MROWS (BSZ * LSEQ)   // 4096
#define KDIM 2048
#define SCALE_F 0.08838834764831845f

// ---------------------------------------------------------------------------
// Scratch (__device__ globals; no allocation allowed)
// ---------------------------------------------------------------------------
__device__ __nv_bfloat16 g_xh[(size_t)MROWS * DIMSZ];
__device__ __nv_bfloat16 g_xl[(size_t)MROWS * DIMSZ];
__device__ __nv_bfloat16 g_ch[(size_t)MROWS * DIMSZ];
__device__ __nv_bfloat16 g_cl[(size_t)MROWS * DIMSZ];
__device__ __nv_bfloat16 g_wqh[(size_t)3 * DIMSZ * DIMSZ];  // W_qkv^T [6144][2048]
__device__ __nv_bfloat16 g_wql[(size_t)3 * DIMSZ * DIMSZ];
__device__ __nv_bfloat16 g_wph[(size_t)DIMSZ * DIMSZ];      // W_proj^T [2048][2048]
__device__ __nv_bfloat16 g_wpl[(size_t)DIMSZ * DIMSZ];
__device__ __nv_bfloat16 g_qh[(size_t)MROWS * DIMSZ];
__device__ __nv_bfloat16 g_ql[(size_t)MROWS * DIMSZ];
__device__ __nv_bfloat16 g_kvh[(size_t)MROWS * 2 * DIMSZ];
__device__ __nv_bfloat16 g_kvl[(size_t)MROWS * 2 * DIMSZ];
__device__ __nv_bfloat16 g_ath[(size_t)MROWS * DIMSZ];
__device__ __nv_bfloat16 g_atl[(size_t)MROWS * DIMSZ];

// ---------------------------------------------------------------------------
// PTX helpers (baseline ISA: ldmatrix / mma.sync / cp.async)
// ---------------------------------------------------------------------------
__device__ __forceinline__ uint32_t smem_to_u32(const void* p) {
    uint32_t a;
    asm("{ .reg .u64 t; cvta.to.shared.u64 t, %1; cvt.u32.u64 %0, t; }" : "=r"(a) : "l"(p));
    return a;
}

#define CP_ASYNC16(dst, src) \
    asm volatile("cp.async.cg.shared.global [%0], [%1], 16;" :: "r"(dst), "l"(src) : "memory")
#define CP_COMMIT() asm volatile("cp.async.commit_group;" ::: "memory")
#define CP_WAIT(n)  asm volatile("cp.async.wait_group %0;" :: "n"(n) : "memory")

#define LDSM_X4(r0, r1, r2, r3, addr) \
    asm volatile("ldmatrix.sync.aligned.m8n8.x4.shared.b16 {%0,%1,%2,%3}, [%4];" \
                 : "=r"(r0), "=r"(r1), "=r"(r2), "=r"(r3) : "r"(addr))
#define LDSM_X4_T(r0, r1, r2, r3, addr) \
    asm volatile("ldmatrix.sync.aligned.m8n8.x4.trans.shared.b16 {%0,%1,%2,%3}, [%4];" \
                 : "=r"(r0), "=r"(r1), "=r"(r2), "=r"(r3) : "r"(addr))

#define MMA16816(d, a, b0, b1) \
    asm volatile("mma.sync.aligned.m16n8k16.row.col.f32.bf16.bf16.f32 " \
                 "{%0,%1,%2,%3}, {%4,%5,%6,%7}, {%8,%9}, {%0,%1,%2,%3};" \
                 : "+f"((d)[0]), "+f"((d)[1]), "+f"((d)[2]), "+f"((d)[3]) \
                 : "r"((a)[0]), "r"((a)[1]), "r"((a)[2]), "r"((a)[3]), \
                   "r"(b0), "r"(b1))

__device__ __forceinline__ uint32_t packbf(float lo, float hi) {
    uint32_t r;
    asm("cvt.rn.bf16x2.f32 %0, %1, %2;" : "=r"(r) : "f"(hi), "f"(lo));
    return r;
}
__device__ __forceinline__ float bflo_f(uint32_t u) { return __uint_as_float(u << 16); }
__device__ __forceinline__ float bfhi_f(uint32_t u) { return __uint_as_float(u & 0xffff0000u); }

// ---------------------------------------------------------------------------
// Conversion kernels
// ---------------------------------------------------------------------------
__global__ __launch_bounds__(256)
void split_fp32(const float* __restrict__ in, __nv_bfloat16* __restrict__ h,
                __nv_bfloat16* __restrict__ l, int n4)
{
    int i = blockIdx.x * 256 + threadIdx.x;
    if (i >= n4) return;
    float4 v = ((const float4*)in)[i];
    uint32_t h01 = packbf(v.x, v.y), h23 = packbf(v.z, v.w);
    uint32_t l01 = packbf(v.x - bflo_f(h01), v.y - bfhi_f(h01));
    uint32_t l23 = packbf(v.z - bflo_f(h23), v.w - bfhi_f(h23));
    ((uint32_t*)h)[2 * i] = h01; ((uint32_t*)h)[2 * i + 1] = h23;
    ((uint32_t*)l)[2 * i] = l01; ((uint32_t*)l)[2 * i + 1] = l23;
}

__global__ __launch_bounds__(256)
void transpose_split(const float* __restrict__ in, __nv_bfloat16* __restrict__ h,
                     __nv_bfloat16* __restrict__ l, int R, int C)
{
    __shared__ float tile[32][33];
    int c0 = blockIdx.x * 32, r0 = blockIdx.y * 32;
    int tx = threadIdx.x & 31, ty = threadIdx.x >> 5;
#pragma unroll
    for (int i = 0; i < 4; i++)
        tile[ty + 8 * i][tx] = in[(size_t)(r0 + ty + 8 * i) * C + c0 + tx];
    __syncthreads();
#pragma unroll
    for (int i = 0; i < 4; i++) {
        float v = tile[tx][ty + 8 * i];
        __nv_bfloat16 hv = __float2bfloat16(v);
        __nv_bfloat16 lv = __float2bfloat16(v - __bfloat162float(hv));
        size_t o = (size_t)(c0 + ty + 8 * i) * R + r0 + tx;
        h[o] = hv; l[o] = lv;
    }
}

// ---------------------------------------------------------------------------
// mma.sync split-bf16 GEMM: C = A @ B^T + bias (3 passes, pass-major order)
// CTA 256x128x32, 8 warps (warp tile 64m x 64n), 3-stage cp.async pipeline.
// ---------------------------------------------------------------------------
#define GBM 256
#define GBN 128
#define GBK 32
#define NCH (KDIM / GBK)         // 64
#define ROWB 80
#define ATB (GBM * ROWB)         // 20480
#define BTB (GBN * ROWB)         // 10240
#define STB (2 * ATB + 2 * BTB)  // 61440
#define NSTAGE 3
#define GEMM_SMEM (NSTAGE * STB) // 184320

__global__ __launch_bounds__(256, 1)
void gemm_mma(const __nv_bfloat16* __restrict__ Ah0, const __nv_bfloat16* __restrict__ Al0,
              const __nv_bfloat16* __restrict__ Ah1, const __nv_bfloat16* __restrict__ Al1,
              const __nv_bfloat16* __restrict__ Bh, const __nv_bfloat16* __restrict__ Bl,
              const float* __restrict__ bias,
              float* __restrict__ Cf0, int ldc0, float* __restrict__ Cf1, int ldc1,
              __nv_bfloat16* __restrict__ Ch0, __nv_bfloat16* __restrict__ Cl0,
              __nv_bfloat16* __restrict__ Ch1, __nv_bfloat16* __restrict__ Cl1,
              int nsplit, int outmode)
{
    extern __shared__ char sm[];
    const uint32_t sbase = smem_to_u32(sm);
    const int tid  = threadIdx.x;
    const int lane = tid & 31;
    const int wid  = tid >> 5;
    const int wm   = (wid & 3) * 64;
    const int wn   = (wid >> 2) * 64;
    const int n0 = blockIdx.x * GBN;
    const int m0 = blockIdx.y * GBM;

    const __nv_bfloat16* Ah = (n0 < nsplit) ? Ah0 : Ah1;
    const __nv_bfloat16* Al = (n0 < nsplit) ? Al0 : Al1;

    float acc[4][8][4];
#pragma unroll
    for (int i = 0; i < 4; i++)
#pragma unroll
        for (int j = 0; j < 8; j++)
#pragma unroll
            for (int r = 0; r < 4; r++) acc[i][j][r] = 0.f;

    uint32_t aoff[4];
#pragma unroll
    for (int mf = 0; mf < 4; mf++)
        aoff[mf] = (uint32_t)((wm + mf * 16 + (lane & 15)) * ROWB + (lane >> 4) * 16);
    uint32_t boff[4];
#pragma unroll
    for (int jj = 0; jj < 4; jj++)
        boff[jj] = (uint32_t)((wn + jj * 16 + (lane & 7) + 8 * (lane >> 4)) * ROWB
                              + ((lane >> 3) & 1) * 16);

    auto load_chunk = [&](int ic, int s) {
        const int k0 = ic * GBK;
        const uint32_t stage = sbase + s * STB;
#pragma unroll
        for (int it = 0; it < 4; it++) {
            const int idx = it * 256 + tid;
            const int row = idx >> 2, seg = idx & 3;
            const size_t g = (size_t)(m0 + row) * KDIM + k0 + seg * 8;
            const uint32_t dst = stage + row * ROWB + seg * 16;
            CP_ASYNC16(dst, Ah + g);
            CP_ASYNC16(dst + ATB, Al + g);
        }
#pragma unroll
        for (int it = 0; it < 2; it++) {
            const int idx = it * 256 + tid;
            const int row = idx >> 2, seg = idx & 3;
            const size_t g = (size_t)(n0 + row) * KDIM + k0 + seg * 8;
            const uint32_t dst = stage + 2 * ATB + row * ROWB + seg * 16;
            CP_ASYNC16(dst, Bh + g);
            CP_ASYNC16(dst + BTB, Bl + g);
        }
        CP_COMMIT();
    };

    load_chunk(0, 0);
    load_chunk(1, 1);

    for (int ic = 0; ic < NCH; ic++) {
        const int s = ic % NSTAGE;
        if (ic + 2 < NCH)      { load_chunk(ic + 2, (ic + 2) % NSTAGE); CP_WAIT(2); }
        else if (ic + 1 < NCH) { CP_WAIT(1); }
        else                   { CP_WAIT(0); }
        __syncthreads();

        const uint32_t sA = sbase + s * STB;
        const uint32_t sB = sA + 2 * ATB;
#pragma unroll
        for (int ks = 0; ks < 2; ks++) {
            // Preload ALL fragments for this K16 step
            uint32_t ah[4][4], al[4][4], bh[4][4], bl[4][4];
#pragma unroll
            for (int mf = 0; mf < 4; mf++) {
                LDSM_X4(ah[mf][0], ah[mf][1], ah[mf][2], ah[mf][3], sA + aoff[mf] + ks * 32);
                LDSM_X4(al[mf][0], al[mf][1], al[mf][2], al[mf][3], sA + ATB + aoff[mf] + ks * 32);
            }
#pragma unroll
            for (int jj = 0; jj < 4; jj++) {
                LDSM_X4(bh[jj][0], bh[jj][1], bh[jj][2], bh[jj][3], sB + boff[jj] + ks * 32);
                LDSM_X4(bl[jj][0], bl[jj][1], bl[jj][2], bl[jj][3], sB + BTB + boff[jj] + ks * 32);
            }
            // Pass-major: same accumulator reused at distance 32
#pragma unroll
            for (int jj = 0; jj < 4; jj++)
#pragma unroll
                for (int mf = 0; mf < 4; mf++) {
                    MMA16816(acc[mf][2 * jj],     ah[mf], bh[jj][0], bh[jj][1]);
                    MMA16816(acc[mf][2 * jj + 1], ah[mf], bh[jj][2], bh[jj][3]);
                }
#pragma unroll
            for (int jj = 0; jj < 4; jj++)
#pragma unroll
                for (int mf = 0; mf < 4; mf++) {
                    MMA16816(acc[mf][2 * jj],     ah[mf], bl[jj][0], bl[jj][1]);
                    MMA16816(acc[mf][2 * jj + 1], ah[mf], bl[jj][2], bl[jj][3]);
                }
#pragma unroll
            for (int jj = 0; jj < 4; jj++)
#pragma unroll
                for (int mf = 0; mf < 4; mf++) {
                    MMA16816(acc[mf][2 * jj],     al[mf], bh[jj][0], bh[jj][1]);
                    MMA16816(acc[mf][2 * jj + 1], al[mf], bh[jj][2], bh[jj][3]);
                }
        }
        __syncthreads();
    }

    int ld, nc0;
    float* Cf; __nv_bfloat16 *Ch, *Cl;
    if (n0 < nsplit) { Cf = Cf0; Ch = Ch0; Cl = Cl0; ld = ldc0; nc0 = n0; }
    else             { Cf = Cf1; Ch = Ch1; Cl = Cl1; ld = ldc1; nc0 = n0 - nsplit; }

#pragma unroll
    for (int mf = 0; mf < 4; mf++) {
#pragma unroll
        for (int nf = 0; nf < 8; nf++) {
            const int nl = wn + nf * 8 + 2 * (lane & 3);
            const float bx = bias[n0 + nl];
            const float by = bias[n0 + nl + 1];
            const int m_up = m0 + wm + mf * 16 + (lane >> 2);
#pragma unroll
            for (int half = 0; half < 2; half++) {
                const int m = m_up + 8 * half;
                float v0 = acc[mf][nf][2 * half]     + bx;
                float v1 = acc[mf][nf][2 * half + 1] + by;
                if (outmode == 0) {
                    float2 v; v.x = v0; v.y = v1;
                    *(float2*)(Cf + (size_t)m * ld + nc0 + nl) = v;
                } else {
                    uint32_t hi = packbf(v0, v1);
                    uint32_t lo = packbf(v0 - bflo_f(hi), v1 - bfhi_f(hi));
                    *(uint32_t*)(Ch + (size_t)m * ld + nc0 + nl) = hi;
                    *(uint32_t*)(Cl + (size_t)m * ld + nc0 + nl) = lo;
                }
            }
        }
    }
}

// ---------------------------------------------------------------------------
// Tensor-core flash attention (split-bf16, 3-pass, pass-major MMA order)
// ---------------------------------------------------------------------------
#define ASTR 272
#define Q_TILE (128 * ASTR)
#define KV_TILE (64 * ASTR)
#define KV_STAGE (4 * KV_TILE)
#define ATT_SMEM (2 * Q_TILE + 2 * KV_STAGE)

__global__ __launch_bounds__(256, 1)
void attn_mma(const __nv_bfloat16* __restrict__ Qh, const __nv_bfloat16* __restrict__ Ql,
              const __nv_bfloat16* __restrict__ KVh, const __nv_bfloat16* __restrict__ KVl,
              __nv_bfloat16* __restrict__ Oh, __nv_bfloat16* __restrict__ Ol)
{
    extern __shared__ char sm[];
    const uint32_t sQh = smem_to_u32(sm);
    const uint32_t sQl = sQh + Q_TILE;
    const uint32_t sKV = sQl + Q_TILE;

    const int tid  = threadIdx.x;
    const int lane = tid & 31;
    const int wid  = tid >> 5;
    const int wm   = wid * 16;

    const int qt = blockIdx.x, h = blockIdx.y, b = blockIdx.z;
    const int qrow0 = b * LSEQ + qt * 128;
    const int hcol  = h * HDIM;

#pragma unroll
    for (int i = 0; i < 8; i++) {
        int idx = i * 256 + tid;
        int row = idx >> 4, seg = idx & 15;
        size_t g = (size_t)(qrow0 + row) * DIMSZ + hcol + seg * 8;
        uint32_t d = row * ASTR + seg * 16;
        CP_ASYNC16(sQh + d, Qh + g);
        CP_ASYNC16(sQl + d, Ql + g);
    }
    CP_COMMIT();

    auto load_kv = [&](int jt, int s) {
        const uint32_t base = sKV + s * KV_STAGE;
        const int krow0 = b * LSEQ + jt * 64;
#pragma unroll
        for (int i = 0; i < 4; i++) {
            int idx = i * 256 + tid;
            int row = idx >> 4, seg = idx & 15;
            size_t roff = (size_t)(krow0 + row) * (2 * DIMSZ);
            uint32_t d = row * ASTR + seg * 16;
            CP_ASYNC16(base + d,               KVh + roff + hcol + seg * 8);
            CP_ASYNC16(base + KV_TILE + d,     KVl + roff + hcol + seg * 8);
            CP_ASYNC16(base + 2 * KV_TILE + d, KVh + roff + DIMSZ + hcol + seg * 8);
            CP_ASYNC16(base + 3 * KV_TILE + d, KVl + roff + DIMSZ + hcol + seg * 8);
        }
        CP_COMMIT();
    };
    load_kv(0, 0);

    const uint32_t ab = (uint32_t)((wm + (lane & 15)) * ASTR + (lane >> 4) * 16);
    const uint32_t kb = (uint32_t)(((lane & 7) + 8 * (lane >> 4)) * ASTR
                                   + ((lane >> 3) & 1) * 16);
    const uint32_t vb = (uint32_t)(((lane & 7) + 8 * ((lane >> 3) & 1)) * ASTR
                                   + (lane >> 4) * 16);

    float oacc[16][4];
#pragma unroll
    for (int f = 0; f < 16; f++)
#pragma unroll
        for (int e = 0; e < 4; e++) oacc[f][e] = 0.f;
    float m_prev[2] = {-3.0e38f, -3.0e38f};
    float l_acc[2]  = {0.f, 0.f};

    for (int jt = 0; jt < LSEQ / 64; jt++) {
        const int s = jt & 1;
        const bool has_next = (jt + 1 < LSEQ / 64);
        if (has_next) load_kv(jt + 1, s ^ 1);
        if (has_next) { CP_WAIT(1); } else { CP_WAIT(0); }
        __syncthreads();

        const uint32_t sK  = sKV + s * KV_STAGE;
        const uint32_t sKl = sK + KV_TILE;
        const uint32_t sV  = sK + 2 * KV_TILE;
        const uint32_t sVl = sK + 3 * KV_TILE;

        float sacc[8][4];
#pragma unroll
        for (int f = 0; f < 8; f++)
#pragma unroll
            for (int e = 0; e < 4; e++) sacc[f][e] = 0.f;

#pragma unroll
        for (int ks = 0; ks < 8; ks++) {
            uint32_t ah[4], al[4], kh[4][4], kl[4][4];
            LDSM_X4(ah[0], ah[1], ah[2], ah[3], sQh + ab + ks * 32);
            LDSM_X4(al[0], al[1], al[2], al[3], sQl + ab + ks * 32);
#pragma unroll
            for (int jj = 0; jj < 4; jj++) {
                LDSM_X4(kh[jj][0], kh[jj][1], kh[jj][2], kh[jj][3],
                        sK + kb + jj * (16 * ASTR) + ks * 32);
                LDSM_X4(kl[jj][0], kl[jj][1], kl[jj][2], kl[jj][3],
                        sKl + kb + jj * (16 * ASTR) + ks * 32);
            }
#pragma unroll
            for (int jj = 0; jj < 4; jj++) {
                MMA16816(sacc[2 * jj],     ah, kh[jj][0], kh[jj][1]);
                MMA16816(sacc[2 * jj + 1], ah, kh[jj][2], kh[jj][3]);
            }
#pragma unroll
            for (int jj = 0; jj < 4; jj++) {
                MMA16816(sacc[2 * jj],     ah, kl[jj][0], kl[jj][1]);
                MMA16816(sacc[2 * jj + 1], ah, kl[jj][2], kl[jj][3]);
            }
#pragma unroll
            for (int jj = 0; jj < 4; jj++) {
                MMA16816(sacc[2 * jj],     al, kh[jj][0], kh[jj][1]);
                MMA16816(sacc[2 * jj + 1], al, kh[jj][2], kh[jj][3]);
            }
        }

        float mx0 = -3.0e38f, mx1 = -3.0e38f;
#pragma unroll
        for (int f = 0; f < 8; f++) {
            sacc[f][0] *= SCALE_F; sacc[f][1] *= SCALE_F;
            sacc[f][2] *= SCALE_F; sacc[f][3] *= SCALE_F;
            mx0 = fmaxf(mx0, fmaxf(sacc[f][0], sacc[f][1]));
            mx1 = fmaxf(mx1, fmaxf(sacc[f][2], sacc[f][3]));
        }
        mx0 = fmaxf(mx0, __shfl_xor_sync(0xffffffffu, mx0, 1));
        mx0 = fmaxf(mx0, __shfl_xor_sync(0xffffffffu, mx0, 2));
        mx1 = fmaxf(mx1, __shfl_xor_sync(0xffffffffu, mx1, 1));
        mx1 = fmaxf(mx1, __shfl_xor_sync(0xffffffffu, mx1, 2));

        float mnew0 = fmaxf(m_prev[0], mx0);
        float mnew1 = fmaxf(m_prev[1], mx1);
        float er0 = __expf(m_prev[0] - mnew0);
        float er1 = __expf(m_prev[1] - mnew1);
        m_prev[0] = mnew0; m_prev[1] = mnew1;

        float rsum0 = 0.f, rsum1 = 0.f;
#pragma unroll
        for (int f = 0; f < 8; f++) {
            sacc[f][0] = __expf(sacc[f][0] - mnew0);
            sacc[f][1] = __expf(sacc[f][1] - mnew0);
            sacc[f][2] = __expf(sacc[f][2] - mnew1);
            sacc[f][3] = __expf(sacc[f][3] - mnew1);
            rsum0 += sacc[f][0] + sacc[f][1];
            rsum1 += sacc[f][2] + sacc[f][3];
        }
        rsum0 += __shfl_xor_sync(0xffffffffu, rsum0, 1);
        rsum0 += __shfl_xor_sync(0xffffffffu, rsum0, 2);
        rsum1 += __shfl_xor_sync(0xffffffffu, rsum1, 1);
        rsum1 += __shfl_xor_sync(0xffffffffu, rsum1, 2);
        l_acc[0] = l_acc[0] * er0 + rsum0;
        l_acc[1] = l_acc[1] * er1 + rsum1;

#pragma unroll
        for (int f = 0; f < 16; f++) {
            oacc[f][0] *= er0; oacc[f][1] *= er0;
            oacc[f][2] *= er1; oacc[f][3] *= er1;
        }

        uint32_t aph[4][4], apl[4][4];
#pragma unroll
        for (int t = 0; t < 4; t++) {
#pragma unroll
            for (int half = 0; half < 2; half++) {
                const int f = 2 * t + half;
                uint32_t u0 = packbf(sacc[f][0], sacc[f][1]);
                uint32_t u1 = packbf(sacc[f][2], sacc[f][3]);
                aph[t][2 * half]     = u0;
                aph[t][2 * half + 1] = u1;
                apl[t][2 * half] =
                    packbf(sacc[f][0] - bflo_f(u0), sacc[f][1] - bfhi_f(u0));
                apl[t][2 * half + 1] =
                    packbf(sacc[f][2] - bflo_f(u1), sacc[f][3] - bfhi_f(u1));
            }
        }

#pragma unroll
        for (int t = 0; t < 4; t++) {
#pragma unroll
            for (int gh = 0; gh < 2; gh++) {
                uint32_t vh[4][4], vl[4][4];
#pragma unroll
                for (int g4 = 0; g4 < 4; g4++) {
                    const int g = gh * 4 + g4;
                    LDSM_X4_T(vh[g4][0], vh[g4][1], vh[g4][2], vh[g4][3],
                              sV + vb + t * (16 * ASTR) + g * 32);
                    LDSM_X4_T(vl[g4][0], vl[g4][1], vl[g4][2], vl[g4][3],
                              sVl + vb + t * (16 * ASTR) + g * 32);
                }
#pragma unroll
                for (int g4 = 0; g4 < 4; g4++) {
                    const int g = gh * 4 + g4;
                    MMA16816(oacc[2 * g],     aph[t], vh[g4][0], vh[g4][1]);
                    MMA16816(oacc[2 * g + 1], aph[t], vh[g4][2], vh[g4][3]);
                }
#pragma unroll
                for (int g4 = 0; g4 < 4; g4++) {
                    const int g = gh * 4 + g4;
                    MMA16816(oacc[2 * g],     aph[t], vl[g4][0], vl[g4][1]);
                    MMA16816(oacc[2 * g + 1], aph[t], vl[g4][2], vl[g4][3]);
                }
#pragma unroll
                for (int g4 = 0; g4 < 4; g4++) {
                    const int g = gh * 4 + g4;
                    MMA16816(oacc[2 * g],     apl[t], vh[g4][0], vh[g4][1]);
                    MMA16816(oacc[2 * g + 1], apl[t], vh[g4][2], vh[g4][3]);
                }
            }
        }
        __syncthreads();
    }

#pragma unroll
    for (int rs = 0; rs < 2; rs++) {
        const float inv = 1.0f / l_acc[rs];
        const int row = qrow0 + wm + (lane >> 2) + 8 * rs;
#pragma unroll
        for (int f = 0; f < 16; f++) {
            float v0 = oacc[f][2 * rs]     * inv;
            float v1 = oacc[f][2 * rs + 1] * inv;
            uint32_t hi = packbf(v0, v1);
            uint32_t lo = packbf(v0 - bflo_f(hi), v1 - bfhi_f(hi));
            const int col = hcol + f * 8 + 2 * (lane & 3);
            *(uint32_t*)(Oh + (size_t)row * DIMSZ + col) = hi;
            *(uint32_t*)(Ol + (size_t)row * DIMSZ + col) = lo;
        }
    }
}

// ---------------------------------------------------------------------------
extern "C" void kernel_launch(void* const* d_in, const int* in_sizes, int n_in,
                              void* d_out, int out_size)
{
    const float* x       = (const float*)d_in[0];
    const float* context = (const float*)d_in[1];
    const float* W_qkv   = (const float*)d_in[2];
    const float* b_qkv   = (const float*)d_in[3];
    const float* W_proj  = (const float*)d_in[4];
    const float* b_proj  = (const float*)d_in[5];
    float* out = (float*)d_out;

    __nv_bfloat16 *xh, *xl, *ch, *cl, *wqh, *wql, *wph, *wpl;
    __nv_bfloat16 *qh, *ql, *kvh, *kvl, *ath, *atl;
    cudaGetSymbolAddress((void**)&xh,  g_xh);  cudaGetSymbolAddress((void**)&xl,  g_xl);
    cudaGetSymbolAddress((void**)&ch,  g_ch);  cudaGetSymbolAddress((void**)&cl,  g_cl);
    cudaGetSymbolAddress((void**)&wqh, g_wqh); cudaGetSymbolAddress((void**)&wql, g_wql);
    cudaGetSymbolAddress((void**)&wph, g_wph); cudaGetSymbolAddress((void**)&wpl, g_wpl);
    cudaGetSymbolAddress((void**)&qh,  g_qh);  cudaGetSymbolAddress((void**)&ql,  g_ql);
    cudaGetSymbolAddress((void**)&kvh, g_kvh); cudaGetSymbolAddress((void**)&kvl, g_kvl);
    cudaGetSymbolAddress((void**)&ath, g_ath); cudaGetSymbolAddress((void**)&atl, g_atl);

    cudaFuncSetAttribute(gemm_mma, cudaFuncAttributeMaxDynamicSharedMemorySize, GEMM_SMEM);
    cudaFuncSetAttribute(attn_mma, cudaFuncAttributeMaxDynamicSharedMemorySize, ATT_SMEM);

    const int n4 = MROWS * DIMSZ / 4;

    split_fp32<<<(n4 + 255) / 256, 256>>>(x, xh, xl, n4);
    split_fp32<<<(n4 + 255) / 256, 256>>>(context, ch, cl, n4);
    transpose_split<<<dim3(3 * DIMSZ / 32, DIMSZ / 32), 256>>>(W_qkv, wqh, wql, DIMSZ, 3 * DIMSZ);
    transpose_split<<<dim3(DIMSZ / 32, DIMSZ / 32), 256>>>(W_proj, wph, wpl, DIMSZ, DIMSZ);

    gemm_mma<<<dim3(3 * DIMSZ / GBN, MROWS / GBM), 256, GEMM_SMEM>>>(
        xh, xl, ch, cl, wqh, wql, b_qkv,
        nullptr, DIMSZ, nullptr, 2 * DIMSZ,
        qh, ql, kvh, kvl, DIMSZ, 1);

    attn_mma<<<dim3(LSEQ / 128, NHEADS, BSZ), 256, ATT_SMEM>>>(qh, ql, kvh, kvl, ath, atl);

    gemm_mma<<<dim3(DIMSZ / GBN, MROWS / GBM), 256, GEMM_SMEM>>>(
        ath, atl, ath, atl, wph, wpl, b_proj,
        out, DIMSZ, out, DIMSZ,
        nullptr, nullptr, nullptr, nullptr, 1 << 30, 0);
}

// round 7
// speedup vs baseline: 2.5512x; 1.0234x over previous
#include <cuda_runtime.h>
#include <cuda_bf16.h>
#include <cstdint>

#define DIMSZ 2048
#define NHEADS 16
#define HDIM 128
#define BSZ 2
#define LSEQ 2048
#define MROWS (BSZ * LSEQ)   // 4096
#define KDIM 2048
#define SCALE_F 0.08838834764831845f

// ---------------------------------------------------------------------------
// Scratch (__device__ globals; no allocation allowed)
// ---------------------------------------------------------------------------
__device__ __nv_bfloat16 g_xh[(size_t)MROWS * DIMSZ];
__device__ __nv_bfloat16 g_xl[(size_t)MROWS * DIMSZ];
__device__ __nv_bfloat16 g_ch[(size_t)MROWS * DIMSZ];
__device__ __nv_bfloat16 g_cl[(size_t)MROWS * DIMSZ];
__device__ __nv_bfloat16 g_wqh[(size_t)3 * DIMSZ * DIMSZ];  // W_qkv^T [6144][2048]
__device__ __nv_bfloat16 g_wql[(size_t)3 * DIMSZ * DIMSZ];
__device__ __nv_bfloat16 g_wph[(size_t)DIMSZ * DIMSZ];      // W_proj^T [2048][2048]
__device__ __nv_bfloat16 g_wpl[(size_t)DIMSZ * DIMSZ];
__device__ __nv_bfloat16 g_qh[(size_t)MROWS * DIMSZ];
__device__ __nv_bfloat16 g_ql[(size_t)MROWS * DIMSZ];
__device__ __nv_bfloat16 g_kvh[(size_t)MROWS * 2 * DIMSZ];
__device__ __nv_bfloat16 g_kvl[(size_t)MROWS * 2 * DIMSZ];
__device__ __nv_bfloat16 g_ath[(size_t)MROWS * DIMSZ];
__device__ __nv_bfloat16 g_atl[(size_t)MROWS * DIMSZ];

// ---------------------------------------------------------------------------
// PTX helpers (baseline ISA: ldmatrix / mma.sync / cp.async)
// ---------------------------------------------------------------------------
__device__ __forceinline__ uint32_t smem_to_u32(const void* p) {
    uint32_t a;
    asm("{ .reg .u64 t; cvta.to.shared.u64 t, %1; cvt.u32.u64 %0, t; }" : "=r"(a) : "l"(p));
    return a;
}

#define CP_ASYNC16(dst, src) \
    asm volatile("cp.async.cg.shared.global [%0], [%1], 16;" :: "r"(dst), "l"(src) : "memory")
#define CP_COMMIT() asm volatile("cp.async.commit_group;" ::: "memory")
#define CP_WAIT(n)  asm volatile("cp.async.wait_group %0;" :: "n"(n) : "memory")

#define LDSM_X4(r0, r1, r2, r3, addr) \
    asm volatile("ldmatrix.sync.aligned.m8n8.x4.shared.b16 {%0,%1,%2,%3}, [%4];" \
                 : "=r"(r0), "=r"(r1), "=r"(r2), "=r"(r3) : "r"(addr))
#define LDSM_X4_T(r0, r1, r2, r3, addr) \
    asm volatile("ldmatrix.sync.aligned.m8n8.x4.trans.shared.b16 {%0,%1,%2,%3}, [%4];" \
                 : "=r"(r0), "=r"(r1), "=r"(r2), "=r"(r3) : "r"(addr))

#define MMA16816(d, a, b0, b1) \
    asm volatile("mma.sync.aligned.m16n8k16.row.col.f32.bf16.bf16.f32 " \
                 "{%0,%1,%2,%3}, {%4,%5,%6,%7}, {%8,%9}, {%0,%1,%2,%3};" \
                 : "+f"((d)[0]), "+f"((d)[1]), "+f"((d)[2]), "+f"((d)[3]) \
                 : "r"((a)[0]), "r"((a)[1]), "r"((a)[2]), "r"((a)[3]), \
                   "r"(b0), "r"(b1))

__device__ __forceinline__ uint32_t packbf(float lo, float hi) {
    uint32_t r;
    asm("cvt.rn.bf16x2.f32 %0, %1, %2;" : "=r"(r) : "f"(hi), "f"(lo));
    return r;
}
__device__ __forceinline__ float bflo_f(uint32_t u) { return __uint_as_float(u << 16); }
__device__ __forceinline__ float bfhi_f(uint32_t u) { return __uint_as_float(u & 0xffff0000u); }

// ---------------------------------------------------------------------------
// Conversion kernels
// ---------------------------------------------------------------------------
__global__ __launch_bounds__(256)
void split_fp32(const float* __restrict__ in, __nv_bfloat16* __restrict__ h,
                __nv_bfloat16* __restrict__ l, int n4)
{
    int i = blockIdx.x * 256 + threadIdx.x;
    if (i >= n4) return;
    float4 v = ((const float4*)in)[i];
    uint32_t h01 = packbf(v.x, v.y), h23 = packbf(v.z, v.w);
    uint32_t l01 = packbf(v.x - bflo_f(h01), v.y - bfhi_f(h01));
    uint32_t l23 = packbf(v.z - bflo_f(h23), v.w - bfhi_f(h23));
    ((uint32_t*)h)[2 * i] = h01; ((uint32_t*)h)[2 * i + 1] = h23;
    ((uint32_t*)l)[2 * i] = l01; ((uint32_t*)l)[2 * i + 1] = l23;
}

__global__ __launch_bounds__(256)
void transpose_split(const float* __restrict__ in, __nv_bfloat16* __restrict__ h,
                     __nv_bfloat16* __restrict__ l, int R, int C)
{
    __shared__ float tile[32][33];
    int c0 = blockIdx.x * 32, r0 = blockIdx.y * 32;
    int tx = threadIdx.x & 31, ty = threadIdx.x >> 5;
#pragma unroll
    for (int i = 0; i < 4; i++)
        tile[ty + 8 * i][tx] = in[(size_t)(r0 + ty + 8 * i) * C + c0 + tx];
    __syncthreads();
#pragma unroll
    for (int i = 0; i < 4; i++) {
        float v = tile[tx][ty + 8 * i];
        __nv_bfloat16 hv = __float2bfloat16(v);
        __nv_bfloat16 lv = __float2bfloat16(v - __bfloat162float(hv));
        size_t o = (size_t)(c0 + ty + 8 * i) * R + r0 + tx;
        h[o] = hv; l[o] = lv;
    }
}

// ---------------------------------------------------------------------------
// mma.sync split-bf16 GEMM: C = A @ B^T + bias (3 passes)
// CTA 128x128x32, 8 warps (warp tile 32m x 64n), double-buffered cp.async,
// 2 CTAs/SM (launch_bounds 256,2): 4 warps per SMSP for latency hiding.
// ---------------------------------------------------------------------------
#define GBM 128
#define GBN 128
#define GBK 32
#define NCH (KDIM / GBK)         // 64
#define ROWB 80
#define TILE_B (128 * ROWB)      // 10240
#define STAGE_B (4 * TILE_B)     // 40960 : [Ah][Al][Bh][Bl]
#define GEMM_SMEM (2 * STAGE_B)  // 81920

__global__ __launch_bounds__(256, 2)
void gemm_mma(const __nv_bfloat16* __restrict__ Ah0, const __nv_bfloat16* __restrict__ Al0,
              const __nv_bfloat16* __restrict__ Ah1, const __nv_bfloat16* __restrict__ Al1,
              const __nv_bfloat16* __restrict__ Bh, const __nv_bfloat16* __restrict__ Bl,
              const float* __restrict__ bias,
              float* __restrict__ Cf0, int ldc0, float* __restrict__ Cf1, int ldc1,
              __nv_bfloat16* __restrict__ Ch0, __nv_bfloat16* __restrict__ Cl0,
              __nv_bfloat16* __restrict__ Ch1, __nv_bfloat16* __restrict__ Cl1,
              int nsplit, int outmode)
{
    extern __shared__ char sm[];
    const uint32_t sbase = smem_to_u32(sm);
    const int tid  = threadIdx.x;
    const int lane = tid & 31;
    const int wid  = tid >> 5;
    const int wm   = (wid & 3) * 32;   // warp m offset
    const int wn   = (wid >> 2) * 64;  // warp n offset
    const int n0 = blockIdx.x * GBN;
    const int m0 = blockIdx.y * GBM;

    const __nv_bfloat16* Ah = (n0 < nsplit) ? Ah0 : Ah1;
    const __nv_bfloat16* Al = (n0 < nsplit) ? Al0 : Al1;

    float acc[2][8][4];
#pragma unroll
    for (int i = 0; i < 2; i++)
#pragma unroll
        for (int j = 0; j < 8; j++)
#pragma unroll
            for (int r = 0; r < 4; r++) acc[i][j][r] = 0.f;

    uint32_t aoff[2][2];
#pragma unroll
    for (int mf = 0; mf < 2; mf++)
#pragma unroll
        for (int ks = 0; ks < 2; ks++)
            aoff[mf][ks] = (uint32_t)((wm + mf * 16 + (lane & 15)) * ROWB
                                      + (ks * 16 + 8 * (lane >> 4)) * 2);
    uint32_t boff[4][2];
#pragma unroll
    for (int jj = 0; jj < 4; jj++)
#pragma unroll
        for (int ks = 0; ks < 2; ks++)
            boff[jj][ks] = (uint32_t)((wn + jj * 16 + (lane & 7) + 8 * (lane >> 4)) * ROWB
                                      + (ks * 16 + 8 * ((lane >> 3) & 1)) * 2);

    auto load_chunk = [&](int ic, int s) {
        const int k0 = ic * GBK;
#pragma unroll
        for (int it = 0; it < 8; it++) {
            const int tile   = it >> 1;                 // 0:Ah 1:Al 2:Bh 3:Bl
            const int within = (it & 1) * 256 + tid;
            const int row    = within >> 2;
            const int seg    = within & 3;
            const __nv_bfloat16* src;
            if (tile == 0)      src = Ah + (size_t)(m0 + row) * KDIM + k0 + seg * 8;
            else if (tile == 1) src = Al + (size_t)(m0 + row) * KDIM + k0 + seg * 8;
            else if (tile == 2) src = Bh + (size_t)(n0 + row) * KDIM + k0 + seg * 8;
            else                src = Bl + (size_t)(n0 + row) * KDIM + k0 + seg * 8;
            uint32_t dst = sbase + s * STAGE_B + tile * TILE_B + row * ROWB + seg * 16;
            CP_ASYNC16(dst, src);
        }
        CP_COMMIT();
    };

    load_chunk(0, 0);

    for (int ic = 0; ic < NCH; ic++) {
        const int s = ic & 1;
        if (ic + 1 < NCH) { load_chunk(ic + 1, s ^ 1); CP_WAIT(1); }
        else              { CP_WAIT(0); }
        __syncthreads();

        const uint32_t stage = sbase + s * STAGE_B;
        // 3 passes: (Ah,Bh), (Ah,Bl), (Al,Bh)
#pragma unroll
        for (int pass = 0; pass < 3; pass++) {
            const uint32_t Abase = stage + ((pass == 2) ? TILE_B : 0);
            const uint32_t Bbase = stage + 2 * TILE_B + ((pass == 1) ? TILE_B : 0);
#pragma unroll
            for (int ks = 0; ks < 2; ks++) {
                uint32_t a[2][4];
                LDSM_X4(a[0][0], a[0][1], a[0][2], a[0][3], Abase + aoff[0][ks]);
                LDSM_X4(a[1][0], a[1][1], a[1][2], a[1][3], Abase + aoff[1][ks]);
#pragma unroll
                for (int jj = 0; jj < 4; jj++) {
                    uint32_t b0, b1, b2, b3;
                    LDSM_X4(b0, b1, b2, b3, Bbase + boff[jj][ks]);
                    MMA16816(acc[0][jj * 2],     a[0], b0, b1);
                    MMA16816(acc[1][jj * 2],     a[1], b0, b1);
                    MMA16816(acc[0][jj * 2 + 1], a[0], b2, b3);
                    MMA16816(acc[1][jj * 2 + 1], a[1], b2, b3);
                }
            }
        }
        __syncthreads();
    }

    // Epilogue
    int ld, nc0;
    float* Cf; __nv_bfloat16 *Ch, *Cl;
    if (n0 < nsplit) { Cf = Cf0; Ch = Ch0; Cl = Cl0; ld = ldc0; nc0 = n0; }
    else             { Cf = Cf1; Ch = Ch1; Cl = Cl1; ld = ldc1; nc0 = n0 - nsplit; }

#pragma unroll
    for (int mf = 0; mf < 2; mf++) {
#pragma unroll
        for (int nf = 0; nf < 8; nf++) {
            const int nl = wn + nf * 8 + 2 * (lane & 3);
            const float bx = bias[n0 + nl];
            const float by = bias[n0 + nl + 1];
            const int m_up = m0 + wm + mf * 16 + (lane >> 2);
#pragma unroll
            for (int half = 0; half < 2; half++) {
                const int m = m_up + 8 * half;
                float v0 = acc[mf][nf][2 * half]     + bx;
                float v1 = acc[mf][nf][2 * half + 1] + by;
                if (outmode == 0) {
                    float2 v; v.x = v0; v.y = v1;
                    *(float2*)(Cf + (size_t)m * ld + nc0 + nl) = v;
                } else {
                    uint32_t hi = packbf(v0, v1);
                    uint32_t lo = packbf(v0 - bflo_f(hi), v1 - bfhi_f(hi));
                    *(uint32_t*)(Ch + (size_t)m * ld + nc0 + nl) = hi;
                    *(uint32_t*)(Cl + (size_t)m * ld + nc0 + nl) = lo;
                }
            }
        }
    }
}

// ---------------------------------------------------------------------------
// Tensor-core flash attention (split-bf16, 3-pass) — unchanged from R6
// ---------------------------------------------------------------------------
#define ASTR 272
#define Q_TILE (128 * ASTR)
#define KV_TILE (64 * ASTR)
#define KV_STAGE (4 * KV_TILE)
#define ATT_SMEM (2 * Q_TILE + 2 * KV_STAGE)

__global__ __launch_bounds__(256, 1)
void attn_mma(const __nv_bfloat16* __restrict__ Qh, const __nv_bfloat16* __restrict__ Ql,
              const __nv_bfloat16* __restrict__ KVh, const __nv_bfloat16* __restrict__ KVl,
              __nv_bfloat16* __restrict__ Oh, __nv_bfloat16* __restrict__ Ol)
{
    extern __shared__ char sm[];
    const uint32_t sQh = smem_to_u32(sm);
    const uint32_t sQl = sQh + Q_TILE;
    const uint32_t sKV = sQl + Q_TILE;

    const int tid  = threadIdx.x;
    const int lane = tid & 31;
    const int wid  = tid >> 5;
    const int wm   = wid * 16;

    const int qt = blockIdx.x, h = blockIdx.y, b = blockIdx.z;
    const int qrow0 = b * LSEQ + qt * 128;
    const int hcol  = h * HDIM;

#pragma unroll
    for (int i = 0; i < 8; i++) {
        int idx = i * 256 + tid;
        int row = idx >> 4, seg = idx & 15;
        size_t g = (size_t)(qrow0 + row) * DIMSZ + hcol + seg * 8;
        uint32_t d = row * ASTR + seg * 16;
        CP_ASYNC16(sQh + d, Qh + g);
        CP_ASYNC16(sQl + d, Ql + g);
    }
    CP_COMMIT();

    auto load_kv = [&](int jt, int s) {
        const uint32_t base = sKV + s * KV_STAGE;
        const int krow0 = b * LSEQ + jt * 64;
#pragma unroll
        for (int i = 0; i < 4; i++) {
            int idx = i * 256 + tid;
            int row = idx >> 4, seg = idx & 15;
            size_t roff = (size_t)(krow0 + row) * (2 * DIMSZ);
            uint32_t d = row * ASTR + seg * 16;
            CP_ASYNC16(base + d,               KVh + roff + hcol + seg * 8);
            CP_ASYNC16(base + KV_TILE + d,     KVl + roff + hcol + seg * 8);
            CP_ASYNC16(base + 2 * KV_TILE + d, KVh + roff + DIMSZ + hcol + seg * 8);
            CP_ASYNC16(base + 3 * KV_TILE + d, KVl + roff + DIMSZ + hcol + seg * 8);
        }
        CP_COMMIT();
    };
    load_kv(0, 0);

    const uint32_t ab = (uint32_t)((wm + (lane & 15)) * ASTR + (lane >> 4) * 16);
    const uint32_t kb = (uint32_t)(((lane & 7) + 8 * (lane >> 4)) * ASTR
                                   + ((lane >> 3) & 1) * 16);
    const uint32_t vb = (uint32_t)(((lane & 7) + 8 * ((lane >> 3) & 1)) * ASTR
                                   + (lane >> 4) * 16);

    float oacc[16][4];
#pragma unroll
    for (int f = 0; f < 16; f++)
#pragma unroll
        for (int e = 0; e < 4; e++) oacc[f][e] = 0.f;
    float m_prev[2] = {-3.0e38f, -3.0e38f};
    float l_acc[2]  = {0.f, 0.f};

    for (int jt = 0; jt < LSEQ / 64; jt++) {
        const int s = jt & 1;
        const bool has_next = (jt + 1 < LSEQ / 64);
        if (has_next) load_kv(jt + 1, s ^ 1);
        if (has_next) { CP_WAIT(1); } else { CP_WAIT(0); }
        __syncthreads();

        const uint32_t sK  = sKV + s * KV_STAGE;
        const uint32_t sKl = sK + KV_TILE;
        const uint32_t sV  = sK + 2 * KV_TILE;
        const uint32_t sVl = sK + 3 * KV_TILE;

        float sacc[8][4];
#pragma unroll
        for (int f = 0; f < 8; f++)
#pragma unroll
            for (int e = 0; e < 4; e++) sacc[f][e] = 0.f;

#pragma unroll
        for (int ks = 0; ks < 8; ks++) {
            uint32_t ah[4], al[4];
            LDSM_X4(ah[0], ah[1], ah[2], ah[3], sQh + ab + ks * 32);
            LDSM_X4(al[0], al[1], al[2], al[3], sQl + ab + ks * 32);
#pragma unroll
            for (int jj = 0; jj < 4; jj++) {
                uint32_t h0, h1, h2, h3, l0, l1, l2, l3;
                LDSM_X4(h0, h1, h2, h3, sK  + kb + jj * (16 * ASTR) + ks * 32);
                LDSM_X4(l0, l1, l2, l3, sKl + kb + jj * (16 * ASTR) + ks * 32);
                MMA16816(sacc[2 * jj],     ah, h0, h1);
                MMA16816(sacc[2 * jj + 1], ah, h2, h3);
                MMA16816(sacc[2 * jj],     ah, l0, l1);
                MMA16816(sacc[2 * jj + 1], ah, l2, l3);
                MMA16816(sacc[2 * jj],     al, h0, h1);
                MMA16816(sacc[2 * jj + 1], al, h2, h3);
            }
        }

        float mx0 = -3.0e38f, mx1 = -3.0e38f;
#pragma unroll
        for (int f = 0; f < 8; f++) {
            sacc[f][0] *= SCALE_F; sacc[f][1] *= SCALE_F;
            sacc[f][2] *= SCALE_F; sacc[f][3] *= SCALE_F;
            mx0 = fmaxf(mx0, fmaxf(sacc[f][0], sacc[f][1]));
            mx1 = fmaxf(mx1, fmaxf(sacc[f][2], sacc[f][3]));
        }
        mx0 = fmaxf(mx0, __shfl_xor_sync(0xffffffffu, mx0, 1));
        mx0 = fmaxf(mx0, __shfl_xor_sync(0xffffffffu, mx0, 2));
        mx1 = fmaxf(mx1, __shfl_xor_sync(0xffffffffu, mx1, 1));
        mx1 = fmaxf(mx1, __shfl_xor_sync(0xffffffffu, mx1, 2));

        float mnew0 = fmaxf(m_prev[0], mx0);
        float mnew1 = fmaxf(m_prev[1], mx1);
        float er0 = __expf(m_prev[0] - mnew0);
        float er1 = __expf(m_prev[1] - mnew1);
        m_prev[0] = mnew0; m_prev[1] = mnew1;

        float rsum0 = 0.f, rsum1 = 0.f;
#pragma unroll
        for (int f = 0; f < 8; f++) {
            sacc[f][0] = __expf(sacc[f][0] - mnew0);
            sacc[f][1] = __expf(sacc[f][1] - mnew0);
            sacc[f][2] = __expf(sacc[f][2] - mnew1);
            sacc[f][3] = __expf(sacc[f][3] - mnew1);
            rsum0 += sacc[f][0] + sacc[f][1];
            rsum1 += sacc[f][2] + sacc[f][3];
        }
        rsum0 += __shfl_xor_sync(0xffffffffu, rsum0, 1);
        rsum0 += __shfl_xor_sync(0xffffffffu, rsum0, 2);
        rsum1 += __shfl_xor_sync(0xffffffffu, rsum1, 1);
        rsum1 += __shfl_xor_sync(0xffffffffu, rsum1, 2);
        l_acc[0] = l_acc[0] * er0 + rsum0;
        l_acc[1] = l_acc[1] * er1 + rsum1;

#pragma unroll
        for (int f = 0; f < 16; f++) {
            oacc[f][0] *= er0; oacc[f][1] *= er0;
            oacc[f][2] *= er1; oacc[f][3] *= er1;
        }

        uint32_t aph[4][4], apl[4][4];
#pragma unroll
        for (int t = 0; t < 4; t++) {
#pragma unroll
            for (int half = 0; half < 2; half++) {
                const int f = 2 * t + half;
                uint32_t u0 = packbf(sacc[f][0], sacc[f][1]);
                uint32_t u1 = packbf(sacc[f][2], sacc[f][3]);
                aph[t][2 * half]     = u0;
                aph[t][2 * half + 1] = u1;
                apl[t][2 * half] =
                    packbf(sacc[f][0] - bflo_f(u0), sacc[f][1] - bfhi_f(u0));
                apl[t][2 * half + 1] =
                    packbf(sacc[f][2] - bflo_f(u1), sacc[f][3] - bfhi_f(u1));
            }
        }

#pragma unroll
        for (int t = 0; t < 4; t++) {
#pragma unroll
            for (int g = 0; g < 8; g++) {
                uint32_t h0, h1, h2, h3, l0, l1, l2, l3;
                LDSM_X4_T(h0, h1, h2, h3, sV  + vb + t * (16 * ASTR) + g * 32);
                LDSM_X4_T(l0, l1, l2, l3, sVl + vb + t * (16 * ASTR) + g * 32);
                MMA16816(oacc[2 * g],     aph[t], h0, h1);
                MMA16816(oacc[2 * g + 1], aph[t], h2, h3);
                MMA16816(oacc[2 * g],     aph[t], l0, l1);
                MMA16816(oacc[2 * g + 1], aph[t], l2, l3);
                MMA16816(oacc[2 * g],     apl[t], h0, h1);
                MMA16816(oacc[2 * g + 1], apl[t], h2, h3);
            }
        }
        __syncthreads();
    }

#pragma unroll
    for (int rs = 0; rs < 2; rs++) {
        const float inv = 1.0f / l_acc[rs];
        const int row = qrow0 + wm + (lane >> 2) + 8 * rs;
#pragma unroll
        for (int f = 0; f < 16; f++) {
            float v0 = oacc[f][2 * rs]     * inv;
            float v1 = oacc[f][2 * rs + 1] * inv;
            uint32_t hi = packbf(v0, v1);
            uint32_t lo = packbf(v0 - bflo_f(hi), v1 - bfhi_f(hi));
            const int col = hcol + f * 8 + 2 * (lane & 3);
            *(uint32_t*)(Oh + (size_t)row * DIMSZ + col) = hi;
            *(uint32_t*)(Ol + (size_t)row * DIMSZ + col) = lo;
        }
    }
}

// ---------------------------------------------------------------------------
extern "C" void kernel_launch(void* const* d_in, const int* in_sizes, int n_in,
                              void* d_out, int out_size)
{
    const float* x       = (const float*)d_in[0];
    const float* context = (const float*)d_in[1];
    const float* W_qkv   = (const float*)d_in[2];
    const float* b_qkv   = (const float*)d_in[3];
    const float* W_proj  = (const float*)d_in[4];
    const float* b_proj  = (const float*)d_in[5];
    float* out = (float*)d_out;

    __nv_bfloat16 *xh, *xl, *ch, *cl, *wqh, *wql, *wph, *wpl;
    __nv_bfloat16 *qh, *ql, *kvh, *kvl, *ath, *atl;
    cudaGetSymbolAddress((void**)&xh,  g_xh);  cudaGetSymbolAddress((void**)&xl,  g_xl);
    cudaGetSymbolAddress((void**)&ch,  g_ch);  cudaGetSymbolAddress((void**)&cl,  g_cl);
    cudaGetSymbolAddress((void**)&wqh, g_wqh); cudaGetSymbolAddress((void**)&wql, g_wql);
    cudaGetSymbolAddress((void**)&wph, g_wph); cudaGetSymbolAddress((void**)&wpl, g_wpl);
    cudaGetSymbolAddress((void**)&qh,  g_qh);  cudaGetSymbolAddress((void**)&ql,  g_ql);
    cudaGetSymbolAddress((void**)&kvh, g_kvh); cudaGetSymbolAddress((void**)&kvl, g_kvl);
    cudaGetSymbolAddress((void**)&ath, g_ath); cudaGetSymbolAddress((void**)&atl, g_atl);

    cudaFuncSetAttribute(gemm_mma, cudaFuncAttributeMaxDynamicSharedMemorySize, GEMM_SMEM);
    cudaFuncSetAttribute(attn_mma, cudaFuncAttributeMaxDynamicSharedMemorySize, ATT_SMEM);

    const int n4 = MROWS * DIMSZ / 4;

    split_fp32<<<(n4 + 255) / 256, 256>>>(x, xh, xl, n4);
    split_fp32<<<(n4 + 255) / 256, 256>>>(context, ch, cl, n4);
    transpose_split<<<dim3(3 * DIMSZ / 32, DIMSZ / 32), 256>>>(W_qkv, wqh, wql, DIMSZ, 3 * DIMSZ);
    transpose_split<<<dim3(DIMSZ / 32, DIMSZ / 32), 256>>>(W_proj, wph, wpl, DIMSZ, DIMSZ);

    gemm_mma<<<dim3(3 * DIMSZ / GBN, MROWS / GBM), 256, GEMM_SMEM>>>(
        xh, xl, ch, cl, wqh, wql, b_qkv,
        nullptr, DIMSZ, nullptr, 2 * DIMSZ,
        qh, ql, kvh, kvl, DIMSZ, 1);

    attn_mma<<<dim3(LSEQ / 128, NHEADS, BSZ), 256, ATT_SMEM>>>(qh, ql, kvh, kvl, ath, atl);

    gemm_mma<<<dim3(DIMSZ / GBN, MROWS / GBM), 256, GEMM_SMEM>>>(
        ath, atl, ath, atl, wph, wpl, b_proj,
        out, DIMSZ, out, DIMSZ,
        nullptr, nullptr, nullptr, nullptr, 1 << 30, 0);
}